// round 9
// baseline (speedup 1.0000x reference)
#include <cuda_runtime.h>
#include <cuda_bf16.h>
#include <math.h>

#define NROWS 32768
#define NCODE 8192
#define DIM   512

#define BM 128
#define BN 128
#define KS 32
#define KT (DIM / KS)
#define NSTAGE 3
#define LDA 40          // KS + 8 pad (bf16) -> conflict-free ldmatrix, 16B-aligned rows

#define MARGIN 0.02f
#define GMAXC 64

#define SMEM_BYTES (NSTAGE * (BM + BN) * LDA * 2)

// scratch (no allocations allowed)
__device__ float g_x2[NROWS];
__device__ float g_y2[NCODE];
__device__ unsigned int g_rowmax[NROWS];
__device__ int g_cnt[NROWS];
__device__ int g_cand[NROWS * GMAXC];
__device__ int g_bestidx[NROWS];
__device__ __nv_bfloat16 g_xb[NROWS * DIM];
__device__ __nv_bfloat16 g_eb[NCODE * DIM];

__device__ __forceinline__ unsigned int fkey(float v) {
    unsigned int b = __float_as_uint(v);
    return (b & 0x80000000u) ? ~b : (b | 0x80000000u);
}
__device__ __forceinline__ float fkey_inv(unsigned int k) {
    unsigned int b = (k & 0x80000000u) ? (k & 0x7FFFFFFFu) : ~k;
    return __uint_as_float(b);
}

__global__ void init_scratch() {
    int i = blockIdx.x * blockDim.x + threadIdx.x;
    if (i < NROWS) { g_rowmax[i] = 0u; g_cnt[i] = 0; }
}

// FUSED: bf16 convert + strictly sequential scalar fp32 norm (bit-matches
// XLA-CPU reduce; identical op order to the VALIDATED R5-R7 row_norms_seq).
__global__ __launch_bounds__(128)
void conv_norm(const float* __restrict__ m, __nv_bfloat16* __restrict__ d,
               float* __restrict__ out, int rows) {
    int row = blockIdx.x * blockDim.x + threadIdx.x;
    if (row >= rows) return;
    const float4* p = reinterpret_cast<const float4*>(m + (size_t)row * DIM);
    __nv_bfloat162* q = reinterpret_cast<__nv_bfloat162*>(d + (size_t)row * DIM);
    float s = 0.0f;
    #pragma unroll 4
    for (int j = 0; j < DIM / 4; j++) {
        float4 v = p[j];
        s = __fadd_rn(s, __fmul_rn(v.x, v.x));
        s = __fadd_rn(s, __fmul_rn(v.y, v.y));
        s = __fadd_rn(s, __fmul_rn(v.z, v.z));
        s = __fadd_rn(s, __fmul_rn(v.w, v.w));
        q[2 * j]     = __floats2bfloat162_rn(v.x, v.y);
        q[2 * j + 1] = __floats2bfloat162_rn(v.z, v.w);
    }
    out[row] = s;
}

__device__ __forceinline__ void ldsm_x4(unsigned& r0, unsigned& r1, unsigned& r2, unsigned& r3,
                                        const void* ptr) {
    unsigned addr = (unsigned)__cvta_generic_to_shared(ptr);
    asm volatile("ldmatrix.sync.aligned.m8n8.x4.shared.b16 {%0,%1,%2,%3}, [%4];"
                 : "=r"(r0), "=r"(r1), "=r"(r2), "=r"(r3) : "r"(addr));
}
__device__ __forceinline__ void mma_bf16(float* c, const unsigned* a, const unsigned* b) {
    asm volatile(
        "mma.sync.aligned.m16n8k16.row.col.f32.bf16.bf16.f32 "
        "{%0,%1,%2,%3}, {%4,%5,%6,%7}, {%8,%9}, {%0,%1,%2,%3};"
        : "+f"(c[0]), "+f"(c[1]), "+f"(c[2]), "+f"(c[3])
        : "r"(a[0]), "r"(a[1]), "r"(a[2]), "r"(a[3]), "r"(b[0]), "r"(b[1]));
}
__device__ __forceinline__ void cp16(void* dst, const void* src) {
    unsigned d = (unsigned)__cvta_generic_to_shared(dst);
    asm volatile("cp.async.cg.shared.global [%0], [%1], 16;" :: "r"(d), "l"(src));
}
#define CP_COMMIT() asm volatile("cp.async.commit_group;")
#define CP_WAIT1()  asm volatile("cp.async.wait_group 1;")

// fast sqrt on the FMA pipe (no MUFU): rsqrt bit-hack + 2 Newton, ~4e-6 rel
__device__ __forceinline__ float negdist(float x2, float y2, float sxy) {
    float dsq = __fadd_rn(__fadd_rn(x2, y2), __fmul_rn(-2.0f, sxy));
    dsq = fmaxf(dsq, 1e-12f);
    float r = __uint_as_float(0x5f37642fu - (__float_as_uint(dsq) >> 1));
    r = r * fmaf(-0.5f * dsq * r, r, 1.5f);
    r = r * fmaf(-0.5f * dsq * r, r, 1.5f);
    return -(dsq * r);
}

// bf16 tensor-core GEMM (VALIDATED R7 mainloop) + inline candidate admission
__global__ __launch_bounds__(256)
void gemm_bf16(float* __restrict__ dist) {
    extern __shared__ __nv_bfloat16 smem[];
    __nv_bfloat16* As = smem;                            // [NSTAGE][BM][LDA]
    __nv_bfloat16* Bs = smem + NSTAGE * BM * LDA;        // [NSTAGE][BN][LDA]

    int tid = threadIdx.x;
    int wid = tid >> 5, lane = tid & 31;
    int warp_m = wid >> 2, warp_n = wid & 3;             // 2 x 4 warps, warp tile 64x32
    int bm = blockIdx.y * BM, bn = blockIdx.x * BN;

    int lr = tid >> 2;
    int ls = tid & 3;
    const __nv_bfloat16* xg = g_xb + (size_t)bm * DIM;
    const __nv_bfloat16* eg = g_eb + (size_t)bn * DIM;

    float acc[4][4][4] = {};

    auto issue = [&](int kt, int s) {
        const __nv_bfloat16* xsrc = xg + kt * KS;
        const __nv_bfloat16* esrc = eg + kt * KS;
        __nv_bfloat16* Ad = As + (size_t)s * BM * LDA;
        __nv_bfloat16* Bd = Bs + (size_t)s * BN * LDA;
        cp16(Ad + lr * LDA + ls * 8,         xsrc + (size_t)lr * DIM + ls * 8);
        cp16(Ad + (lr + 64) * LDA + ls * 8,  xsrc + (size_t)(lr + 64) * DIM + ls * 8);
        cp16(Bd + lr * LDA + ls * 8,         esrc + (size_t)lr * DIM + ls * 8);
        cp16(Bd + (lr + 64) * LDA + ls * 8,  esrc + (size_t)(lr + 64) * DIM + ls * 8);
    };

    issue(0, 0); CP_COMMIT();
    issue(1, 1); CP_COMMIT();

    int sc = 0, si = 2;
    #pragma unroll 1
    for (int kt = 0; kt < KT; kt++) {
        CP_WAIT1();
        __syncthreads();
        if (kt + NSTAGE - 1 < KT) issue(kt + NSTAGE - 1, si);
        CP_COMMIT();

        const __nv_bfloat16* Ab = As + (size_t)sc * BM * LDA;
        const __nv_bfloat16* Bb = Bs + (size_t)sc * BN * LDA;
        #pragma unroll
        for (int kk = 0; kk < 2; kk++) {
            unsigned a[4][4], b[4][2];
            #pragma unroll
            for (int mi = 0; mi < 4; mi++)
                ldsm_x4(a[mi][0], a[mi][1], a[mi][2], a[mi][3],
                        Ab + (warp_m * 64 + mi * 16 + (lane & 15)) * LDA
                           + kk * 16 + ((lane >> 4) << 3));
            #pragma unroll
            for (int nib = 0; nib < 2; nib++) {
                unsigned r0, r1, r2, r3;
                ldsm_x4(r0, r1, r2, r3,
                        Bb + (warp_n * 32 + nib * 16 + ((lane >> 4) << 3) + (lane & 7)) * LDA
                           + kk * 16 + (((lane >> 3) & 1) << 3));
                b[nib * 2][0] = r0; b[nib * 2][1] = r1;
                b[nib * 2 + 1][0] = r2; b[nib * 2 + 1][1] = r3;
            }
            #pragma unroll
            for (int mi = 0; mi < 4; mi++)
                #pragma unroll
                for (int ni = 0; ni < 4; ni++)
                    mma_bf16(acc[mi][ni], a[mi], b[ni]);
        }
        sc = (sc + 1 == NSTAGE) ? 0 : sc + 1;
        si = (si + 1 == NSTAGE) ? 0 : si + 1;
    }

    // epilogue: dist + per-row running max + inline candidate admission.
    // Admission threshold uses the row max KNOWN SO FAR (monotone increasing),
    // so thr <= final_max - MARGIN always: the true argmax is always admitted.
    int qr = lane >> 2, qc = 2 * (lane & 3);

    #pragma unroll
    for (int mi = 0; mi < 4; mi++)
        #pragma unroll
        for (int h = 0; h < 2; h++) {
            int rg = bm + warp_m * 64 + mi * 16 + h * 8 + qr;
            float x2v = g_x2[rg];
            float dv8[8];
            float lmax = -1e30f;
            #pragma unroll
            for (int ni = 0; ni < 4; ni++) {
                int n0 = bn + warp_n * 32 + ni * 8 + qc;
                float d0 = negdist(x2v, g_y2[n0],     acc[mi][ni][2 * h]);
                float d1 = negdist(x2v, g_y2[n0 + 1], acc[mi][ni][2 * h + 1]);
                *reinterpret_cast<float2*>(&dist[(size_t)rg * NCODE + n0]) = make_float2(d0, d1);
                dv8[2 * ni] = d0; dv8[2 * ni + 1] = d1;
                lmax = fmaxf(lmax, fmaxf(d0, d1));
            }
            // row max across the 4 lanes sharing this row (lane&3 group)
            float v = lmax;
            v = fmaxf(v, __shfl_xor_sync(0xffffffffu, v, 1));
            v = fmaxf(v, __shfl_xor_sync(0xffffffffu, v, 2));
            unsigned old = 0u;
            if ((lane & 3) == 0) old = atomicMax(&g_rowmax[rg], fkey(v));
            old = __shfl_sync(0xffffffffu, old, lane & ~3);
            float prev = fkey_inv(old);                 // fkey_inv(0) = NaN; fmaxf ignores NaN
            float thr = fmaxf(prev, v) - MARGIN;
            #pragma unroll
            for (int t = 0; t < 8; t++) {
                if (dv8[t] >= thr) {
                    int slot = atomicAdd(&g_cnt[rg], 1);
                    if (slot < GMAXC)
                        g_cand[rg * GMAXC + slot] =
                            bn + warp_n * 32 + (t >> 1) * 8 + qc + (t & 1);
                }
            }
        }
}

// EXACT validated chain (sequential ascending-k fmaf + exact epilogue roundings)
__device__ __forceinline__ unsigned long long exact_key(
    const float* __restrict__ xr, const float* __restrict__ e, float x2, int row, int c) {
    const float* er = e + (size_t)c * DIM;
    float s = 0.0f;
    #pragma unroll 8
    for (int k = 0; k < DIM; k++)
        s = fmaf(xr[k], er[k], s);
    float xyv = __fmul_rn(-2.0f, s);
    float t   = __fadd_rn(x2, g_y2[c]);
    float dsq = __fadd_rn(t, xyv);
    float dv  = -sqrtf(fmaxf(dsq, 0.0f));
    return ((unsigned long long)fkey(dv) << 32) | (unsigned int)(NCODE - 1 - c);
}

// one warp per row: re-evaluate admitted candidates exactly; overflowed rows
// (cnt > GMAXC, expected ~0) fall back to an exact inline scan of the dist row.
#define RWARPS 8
__global__ __launch_bounds__(256)
void rescue(const float* __restrict__ x, const float* __restrict__ e,
            const float* __restrict__ dist) {
    int w = threadIdx.x >> 5, lane = threadIdx.x & 31;
    int row = blockIdx.x * RWARPS + w;

    int cnt = g_cnt[row];
    const float* xr = x + (size_t)row * DIM;
    float x2 = g_x2[row];
    unsigned long long key = 0ull;

    if (cnt <= GMAXC) {
        for (int base = 0; base < cnt; base += 32) {
            int idx = base + lane;
            if (idx < cnt)
                key = max(key, exact_key(xr, e, x2, row, g_cand[row * GMAXC + idx]));
        }
    } else {
        // fallback: final threshold, exact eval inline, no cap
        float thr = fkey_inv(g_rowmax[row]) - MARGIN;
        const float4* dp = reinterpret_cast<const float4*>(dist + (size_t)row * NCODE);
        for (int j = lane; j < NCODE / 4; j += 32) {
            float4 v = dp[j];
            #pragma unroll
            for (int q = 0; q < 4; q++) {
                float dv = (q == 0) ? v.x : (q == 1) ? v.y : (q == 2) ? v.z : v.w;
                if (dv >= thr)
                    key = max(key, exact_key(xr, e, x2, row, 4 * j + q));
            }
        }
    }
    #pragma unroll
    for (int off = 16; off > 0; off >>= 1) {
        unsigned long long o = __shfl_xor_sync(0xffffffffu, key, off);
        key = (o > key) ? o : key;
    }
    if (lane == 0)
        g_bestidx[row] = (NCODE - 1) - (int)(unsigned int)(key & 0xFFFFFFFFull);
}

__global__ void finalize(const float* __restrict__ embed,
                         float* __restrict__ out_q,
                         float* __restrict__ out_ind) {
    int row = blockIdx.x;
    int c = g_bestidx[row];
    if (threadIdx.x == 0) out_ind[row] = (float)c;
    const float4* src = reinterpret_cast<const float4*>(embed + (size_t)c * DIM);
    float4* dst = reinterpret_cast<float4*>(out_q + (size_t)row * DIM);
    for (int j = threadIdx.x; j < DIM / 4; j += blockDim.x) dst[j] = src[j];
}

extern "C" void kernel_launch(void* const* d_in, const int* in_sizes, int n_in,
                              void* d_out, int out_size) {
    const float* x = (const float*)d_in[0];      // [32768, 512]
    const float* e = (const float*)d_in[1];      // [8192, 512]
    float* out = (float*)d_out;

    float* out_q    = out;                                   // [N, D]
    float* out_ind  = out + (size_t)NROWS * DIM;             // [N]
    float* out_dist = out + (size_t)NROWS * DIM + NROWS;     // [N, C]

    float *d_x2, *d_y2;
    __nv_bfloat16 *d_xb, *d_eb;
    cudaGetSymbolAddress((void**)&d_x2, g_x2);
    cudaGetSymbolAddress((void**)&d_y2, g_y2);
    cudaGetSymbolAddress((void**)&d_xb, g_xb);
    cudaGetSymbolAddress((void**)&d_eb, g_eb);

    cudaFuncSetAttribute(gemm_bf16, cudaFuncAttributeMaxDynamicSharedMemorySize, SMEM_BYTES);

    init_scratch<<<(NROWS + 255) / 256, 256>>>();
    conv_norm<<<NROWS / 128, 128>>>(x, d_xb, d_x2, NROWS);
    conv_norm<<<NCODE / 128, 128>>>(e, d_eb, d_y2, NCODE);

    dim3 grid(NCODE / BN, NROWS / BM);
    gemm_bf16<<<grid, 256, SMEM_BYTES>>>(out_dist);

    rescue<<<NROWS / RWARPS, 256>>>(x, e, out_dist);

    finalize<<<NROWS, 128>>>(e, out_q, out_ind);
}

// round 10
// speedup vs baseline: 1.2587x; 1.2587x over previous
#include <cuda_runtime.h>
#include <cuda_bf16.h>
#include <math.h>

#define NROWS 32768
#define NCODE 8192
#define DIM   512

#define BM 128
#define BN 128
#define KS 32
#define KT (DIM / KS)
#define NSTAGE 3
#define LDA 40          // KS + 8 pad (bf16) -> conflict-free ldmatrix, 16B-aligned rows

#define MARGIN 0.02f
#define MAXCAND 32

#define SMEM_BYTES (NSTAGE * (BM + BN) * LDA * 2)

// scratch (no allocations allowed)
__device__ float g_x2[NROWS];
__device__ float g_y2[NCODE];
__device__ unsigned int g_rowmax[NROWS];
__device__ int g_bestidx[NROWS];
__device__ __nv_bfloat16 g_xb[NROWS * DIM];
__device__ __nv_bfloat16 g_eb[NCODE * DIM];

__device__ __forceinline__ unsigned int fkey(float v) {
    unsigned int b = __float_as_uint(v);
    return (b & 0x80000000u) ? ~b : (b | 0x80000000u);
}
__device__ __forceinline__ float fkey_inv(unsigned int k) {
    unsigned int b = (k & 0x80000000u) ? (k & 0x7FFFFFFFu) : ~k;
    return __uint_as_float(b);
}

__global__ void init_scratch() {
    int i = blockIdx.x * blockDim.x + threadIdx.x;
    if (i < NROWS) g_rowmax[i] = 0u;
}

// FUSED: bf16 convert + strictly sequential scalar fp32 norm (bit-matches
// XLA-CPU reduce; identical op order to the VALIDATED R5-R7 row_norms_seq).
__global__ __launch_bounds__(128)
void conv_norm(const float* __restrict__ m, __nv_bfloat16* __restrict__ d,
               float* __restrict__ out, int rows) {
    int row = blockIdx.x * blockDim.x + threadIdx.x;
    if (row >= rows) return;
    const float4* p = reinterpret_cast<const float4*>(m + (size_t)row * DIM);
    __nv_bfloat162* q = reinterpret_cast<__nv_bfloat162*>(d + (size_t)row * DIM);
    float s = 0.0f;
    #pragma unroll 4
    for (int j = 0; j < DIM / 4; j++) {
        float4 v = p[j];
        s = __fadd_rn(s, __fmul_rn(v.x, v.x));
        s = __fadd_rn(s, __fmul_rn(v.y, v.y));
        s = __fadd_rn(s, __fmul_rn(v.z, v.z));
        s = __fadd_rn(s, __fmul_rn(v.w, v.w));
        q[2 * j]     = __floats2bfloat162_rn(v.x, v.y);
        q[2 * j + 1] = __floats2bfloat162_rn(v.z, v.w);
    }
    out[row] = s;
}

__device__ __forceinline__ void ldsm_x4(unsigned& r0, unsigned& r1, unsigned& r2, unsigned& r3,
                                        const void* ptr) {
    unsigned addr = (unsigned)__cvta_generic_to_shared(ptr);
    asm volatile("ldmatrix.sync.aligned.m8n8.x4.shared.b16 {%0,%1,%2,%3}, [%4];"
                 : "=r"(r0), "=r"(r1), "=r"(r2), "=r"(r3) : "r"(addr));
}
__device__ __forceinline__ void mma_bf16(float* c, const unsigned* a, const unsigned* b) {
    asm volatile(
        "mma.sync.aligned.m16n8k16.row.col.f32.bf16.bf16.f32 "
        "{%0,%1,%2,%3}, {%4,%5,%6,%7}, {%8,%9}, {%0,%1,%2,%3};"
        : "+f"(c[0]), "+f"(c[1]), "+f"(c[2]), "+f"(c[3])
        : "r"(a[0]), "r"(a[1]), "r"(a[2]), "r"(a[3]), "r"(b[0]), "r"(b[1]));
}
__device__ __forceinline__ void cp16(void* dst, const void* src) {
    unsigned d = (unsigned)__cvta_generic_to_shared(dst);
    asm volatile("cp.async.cg.shared.global [%0], [%1], 16;" :: "r"(d), "l"(src));
}
#define CP_COMMIT() asm volatile("cp.async.commit_group;")
#define CP_WAIT1()  asm volatile("cp.async.wait_group 1;")

// fast sqrt on the FMA pipe (no MUFU): rsqrt bit-hack + 2 Newton, ~4e-6 rel.
// Only feeds the dist output (tolerance 1e-3) and the candidate pre-filter
// (MARGIN 0.02 >> error); the rescue exact chain never sees it.
__device__ __forceinline__ float negdist(float x2, float y2, float sxy) {
    float dsq = __fadd_rn(__fadd_rn(x2, y2), __fmul_rn(-2.0f, sxy));
    dsq = fmaxf(dsq, 1e-12f);
    float r = __uint_as_float(0x5f37642fu - (__float_as_uint(dsq) >> 1));
    r = r * fmaf(-0.5f * dsq * r, r, 1.5f);
    r = r * fmaf(-0.5f * dsq * r, r, 1.5f);
    return -(dsq * r);
}

// bf16 tensor-core GEMM (VALIDATED R7 mainloop), 3 CTAs/SM forced
__global__ __launch_bounds__(256, 3)
void gemm_bf16(float* __restrict__ dist) {
    extern __shared__ __nv_bfloat16 smem[];
    __nv_bfloat16* As = smem;                            // [NSTAGE][BM][LDA]
    __nv_bfloat16* Bs = smem + NSTAGE * BM * LDA;        // [NSTAGE][BN][LDA]

    int tid = threadIdx.x;
    int wid = tid >> 5, lane = tid & 31;
    int warp_m = wid >> 2, warp_n = wid & 3;             // 2 x 4 warps, warp tile 64x32
    int bm = blockIdx.y * BM, bn = blockIdx.x * BN;

    int lr = tid >> 2;
    int ls = tid & 3;
    const __nv_bfloat16* xg = g_xb + (size_t)bm * DIM;
    const __nv_bfloat16* eg = g_eb + (size_t)bn * DIM;

    float acc[4][4][4] = {};

    auto issue = [&](int kt, int s) {
        const __nv_bfloat16* xsrc = xg + kt * KS;
        const __nv_bfloat16* esrc = eg + kt * KS;
        __nv_bfloat16* Ad = As + (size_t)s * BM * LDA;
        __nv_bfloat16* Bd = Bs + (size_t)s * BN * LDA;
        cp16(Ad + lr * LDA + ls * 8,         xsrc + (size_t)lr * DIM + ls * 8);
        cp16(Ad + (lr + 64) * LDA + ls * 8,  xsrc + (size_t)(lr + 64) * DIM + ls * 8);
        cp16(Bd + lr * LDA + ls * 8,         esrc + (size_t)lr * DIM + ls * 8);
        cp16(Bd + (lr + 64) * LDA + ls * 8,  esrc + (size_t)(lr + 64) * DIM + ls * 8);
    };

    issue(0, 0); CP_COMMIT();
    issue(1, 1); CP_COMMIT();

    int sc = 0, si = 2;
    #pragma unroll 1
    for (int kt = 0; kt < KT; kt++) {
        CP_WAIT1();
        __syncthreads();
        if (kt + NSTAGE - 1 < KT) issue(kt + NSTAGE - 1, si);
        CP_COMMIT();

        const __nv_bfloat16* Ab = As + (size_t)sc * BM * LDA;
        const __nv_bfloat16* Bb = Bs + (size_t)sc * BN * LDA;
        #pragma unroll
        for (int kk = 0; kk < 2; kk++) {
            unsigned a[4][4], b[4][2];
            #pragma unroll
            for (int mi = 0; mi < 4; mi++)
                ldsm_x4(a[mi][0], a[mi][1], a[mi][2], a[mi][3],
                        Ab + (warp_m * 64 + mi * 16 + (lane & 15)) * LDA
                           + kk * 16 + ((lane >> 4) << 3));
            #pragma unroll
            for (int nib = 0; nib < 2; nib++) {
                unsigned r0, r1, r2, r3;
                ldsm_x4(r0, r1, r2, r3,
                        Bb + (warp_n * 32 + nib * 16 + ((lane >> 4) << 3) + (lane & 7)) * LDA
                           + kk * 16 + (((lane >> 3) & 1) << 3));
                b[nib * 2][0] = r0; b[nib * 2][1] = r1;
                b[nib * 2 + 1][0] = r2; b[nib * 2 + 1][1] = r3;
            }
            #pragma unroll
            for (int mi = 0; mi < 4; mi++)
                #pragma unroll
                for (int ni = 0; ni < 4; ni++)
                    mma_bf16(acc[mi][ni], a[mi], b[ni]);
        }
        sc = (sc + 1 == NSTAGE) ? 0 : sc + 1;
        si = (si + 1 == NSTAGE) ? 0 : si + 1;
    }

    // epilogue (R7 structure): dist + per-row approx max
    int qr = lane >> 2, qc = 2 * (lane & 3);
    float x2v[4][2], rmax[4][2];
    #pragma unroll
    for (int mi = 0; mi < 4; mi++)
        #pragma unroll
        for (int h = 0; h < 2; h++) {
            x2v[mi][h] = g_x2[bm + warp_m * 64 + mi * 16 + h * 8 + qr];
            rmax[mi][h] = -1e30f;
        }

    #pragma unroll
    for (int ni = 0; ni < 4; ni++) {
        int n0 = bn + warp_n * 32 + ni * 8 + qc;
        float y0 = g_y2[n0], y1 = g_y2[n0 + 1];
        #pragma unroll
        for (int mi = 0; mi < 4; mi++)
            #pragma unroll
            for (int h = 0; h < 2; h++) {
                int rg = bm + warp_m * 64 + mi * 16 + h * 8 + qr;
                float d0 = negdist(x2v[mi][h], y0, acc[mi][ni][2 * h]);
                float d1 = negdist(x2v[mi][h], y1, acc[mi][ni][2 * h + 1]);
                *reinterpret_cast<float2*>(&dist[(size_t)rg * NCODE + n0]) = make_float2(d0, d1);
                rmax[mi][h] = fmaxf(rmax[mi][h], fmaxf(d0, d1));
            }
    }
    #pragma unroll
    for (int mi = 0; mi < 4; mi++)
        #pragma unroll
        for (int h = 0; h < 2; h++) {
            float v = rmax[mi][h];
            v = fmaxf(v, __shfl_xor_sync(0xffffffffu, v, 1));
            v = fmaxf(v, __shfl_xor_sync(0xffffffffu, v, 2));
            if ((lane & 3) == 0)
                atomicMax(&g_rowmax[bm + warp_m * 64 + mi * 16 + h * 8 + qr], fkey(v));
        }
}

// one warp per row: candidates within MARGIN of approx max, re-evaluated with the
// EXACT validated chain (sequential ascending-k fmaf + exact epilogue roundings).
#define RWARPS 8
__global__ __launch_bounds__(256)
void rescue(const float* __restrict__ x, const float* __restrict__ e,
            const float* __restrict__ dist) {
    __shared__ int s_cnt[RWARPS];
    __shared__ int s_cand[RWARPS][MAXCAND];

    int w = threadIdx.x >> 5, lane = threadIdx.x & 31;
    int row = blockIdx.x * RWARPS + w;

    if (lane == 0) s_cnt[w] = 0;
    __syncwarp();

    float thr = fkey_inv(g_rowmax[row]) - MARGIN;
    const float4* dp = reinterpret_cast<const float4*>(dist + (size_t)row * NCODE);
    for (int j = lane; j < NCODE / 4; j += 32) {
        float4 v = dp[j];
        #pragma unroll
        for (int q = 0; q < 4; q++) {
            float dv = (q == 0) ? v.x : (q == 1) ? v.y : (q == 2) ? v.z : v.w;
            if (dv >= thr) {
                int slot = atomicAdd(&s_cnt[w], 1);
                if (slot < MAXCAND) s_cand[w][slot] = 4 * j + q;
            }
        }
    }
    __syncwarp();
    int cnt = s_cnt[w];
    if (cnt > MAXCAND) cnt = MAXCAND;

    unsigned long long key = 0ull;
    if (lane < cnt) {
        int c = s_cand[w][lane];
        const float* xr = x + (size_t)row * DIM;
        const float* er = e + (size_t)c * DIM;
        float s = 0.0f;
        #pragma unroll 8
        for (int k = 0; k < DIM; k++)          // strictly ascending-k fp32 FMA chain
            s = fmaf(xr[k], er[k], s);
        float xyv = __fmul_rn(-2.0f, s);
        float t   = __fadd_rn(g_x2[row], g_y2[c]);
        float dsq = __fadd_rn(t, xyv);
        float dv  = -sqrtf(fmaxf(dsq, 0.0f));
        key = ((unsigned long long)fkey(dv) << 32) | (unsigned int)(NCODE - 1 - c);
    }
    #pragma unroll
    for (int off = 16; off > 0; off >>= 1) {
        unsigned long long o = __shfl_xor_sync(0xffffffffu, key, off);
        key = (o > key) ? o : key;
    }
    if (lane == 0)
        g_bestidx[row] = (NCODE - 1) - (int)(unsigned int)(key & 0xFFFFFFFFull);
}

__global__ void finalize(const float* __restrict__ embed,
                         float* __restrict__ out_q,
                         float* __restrict__ out_ind) {
    int row = blockIdx.x;
    int c = g_bestidx[row];
    if (threadIdx.x == 0) out_ind[row] = (float)c;
    const float4* src = reinterpret_cast<const float4*>(embed + (size_t)c * DIM);
    float4* dst = reinterpret_cast<float4*>(out_q + (size_t)row * DIM);
    for (int j = threadIdx.x; j < DIM / 4; j += blockDim.x) dst[j] = src[j];
}

extern "C" void kernel_launch(void* const* d_in, const int* in_sizes, int n_in,
                              void* d_out, int out_size) {
    const float* x = (const float*)d_in[0];      // [32768, 512]
    const float* e = (const float*)d_in[1];      // [8192, 512]
    float* out = (float*)d_out;

    float* out_q    = out;                                   // [N, D]
    float* out_ind  = out + (size_t)NROWS * DIM;             // [N]
    float* out_dist = out + (size_t)NROWS * DIM + NROWS;     // [N, C]

    float *d_x2, *d_y2;
    __nv_bfloat16 *d_xb, *d_eb;
    cudaGetSymbolAddress((void**)&d_x2, g_x2);
    cudaGetSymbolAddress((void**)&d_y2, g_y2);
    cudaGetSymbolAddress((void**)&d_xb, g_xb);
    cudaGetSymbolAddress((void**)&d_eb, g_eb);

    cudaFuncSetAttribute(gemm_bf16, cudaFuncAttributeMaxDynamicSharedMemorySize, SMEM_BYTES);

    init_scratch<<<(NROWS + 255) / 256, 256>>>();
    conv_norm<<<NROWS / 128, 128>>>(x, d_xb, d_x2, NROWS);
    conv_norm<<<NCODE / 128, 128>>>(e, d_eb, d_y2, NCODE);

    dim3 grid(NCODE / BN, NROWS / BM);
    gemm_bf16<<<grid, 256, SMEM_BYTES>>>(out_dist);

    rescue<<<NROWS / RWARPS, 256>>>(x, e, out_dist);

    finalize<<<NROWS, 128>>>(e, out_q, out_ind);
}

// round 11
// speedup vs baseline: 1.6182x; 1.2856x over previous
#include <cuda_runtime.h>
#include <cuda_bf16.h>
#include <math.h>

#define NROWS 32768
#define NCODE 8192
#define DIM   512

#define BM 128
#define BN 128
#define KS 64
#define KT (DIM / KS)      // 8
#define NSTAGE 3
#define LDA 72          // KS + 8 pad (bf16): 144B row stride -> conflict-free ldmatrix

#define MARGIN 0.02f
#define MAXCAND 32

#define SMEM_BYTES (NSTAGE * (BM + BN) * LDA * 2)   // 110592

// scratch (no allocations allowed)
__device__ float g_x2[NROWS];
__device__ float g_y2[NCODE];
__device__ unsigned int g_rowmax[NROWS];
__device__ int g_bestidx[NROWS];
__device__ __nv_bfloat16 g_xb[NROWS * DIM];
__device__ __nv_bfloat16 g_eb[NCODE * DIM];

__device__ __forceinline__ unsigned int fkey(float v) {
    unsigned int b = __float_as_uint(v);
    return (b & 0x80000000u) ? ~b : (b | 0x80000000u);
}
__device__ __forceinline__ float fkey_inv(unsigned int k) {
    unsigned int b = (k & 0x80000000u) ? (k & 0x7FFFFFFFu) : ~k;
    return __uint_as_float(b);
}

__global__ void init_scratch() {
    int i = blockIdx.x * blockDim.x + threadIdx.x;
    if (i < NROWS) g_rowmax[i] = 0u;
}

// FUSED: bf16 convert + strictly sequential scalar fp32 norm (bit-matches
// XLA-CPU reduce; identical op order to the VALIDATED R5-R7 row_norms_seq).
__global__ __launch_bounds__(128)
void conv_norm(const float* __restrict__ m, __nv_bfloat16* __restrict__ d,
               float* __restrict__ out, int rows) {
    int row = blockIdx.x * blockDim.x + threadIdx.x;
    if (row >= rows) return;
    const float4* p = reinterpret_cast<const float4*>(m + (size_t)row * DIM);
    __nv_bfloat162* q = reinterpret_cast<__nv_bfloat162*>(d + (size_t)row * DIM);
    float s = 0.0f;
    #pragma unroll 4
    for (int j = 0; j < DIM / 4; j++) {
        float4 v = p[j];
        s = __fadd_rn(s, __fmul_rn(v.x, v.x));
        s = __fadd_rn(s, __fmul_rn(v.y, v.y));
        s = __fadd_rn(s, __fmul_rn(v.z, v.z));
        s = __fadd_rn(s, __fmul_rn(v.w, v.w));
        q[2 * j]     = __floats2bfloat162_rn(v.x, v.y);
        q[2 * j + 1] = __floats2bfloat162_rn(v.z, v.w);
    }
    out[row] = s;
}

__device__ __forceinline__ void ldsm_x4(unsigned& r0, unsigned& r1, unsigned& r2, unsigned& r3,
                                        const void* ptr) {
    unsigned addr = (unsigned)__cvta_generic_to_shared(ptr);
    asm volatile("ldmatrix.sync.aligned.m8n8.x4.shared.b16 {%0,%1,%2,%3}, [%4];"
                 : "=r"(r0), "=r"(r1), "=r"(r2), "=r"(r3) : "r"(addr));
}
__device__ __forceinline__ void mma_bf16(float* c, const unsigned* a, const unsigned* b) {
    asm volatile(
        "mma.sync.aligned.m16n8k16.row.col.f32.bf16.bf16.f32 "
        "{%0,%1,%2,%3}, {%4,%5,%6,%7}, {%8,%9}, {%0,%1,%2,%3};"
        : "+f"(c[0]), "+f"(c[1]), "+f"(c[2]), "+f"(c[3])
        : "r"(a[0]), "r"(a[1]), "r"(a[2]), "r"(a[3]), "r"(b[0]), "r"(b[1]));
}
__device__ __forceinline__ void cp16(void* dst, const void* src) {
    unsigned d = (unsigned)__cvta_generic_to_shared(dst);
    asm volatile("cp.async.cg.shared.global [%0], [%1], 16;" :: "r"(d), "l"(src));
}
#define CP_COMMIT() asm volatile("cp.async.commit_group;")
#define CP_WAIT1()  asm volatile("cp.async.wait_group 1;")

// fast sqrt on the FMA pipe (no MUFU): rsqrt bit-hack + 2 Newton, ~4e-6 rel.
// Only feeds the dist output (tolerance 1e-3) and the candidate pre-filter
// (MARGIN 0.02 >> error); the rescue exact chain never sees it.
__device__ __forceinline__ float negdist(float x2, float y2, float sxy) {
    float dsq = __fadd_rn(__fadd_rn(x2, y2), __fmul_rn(-2.0f, sxy));
    dsq = fmaxf(dsq, 1e-12f);
    float r = __uint_as_float(0x5f37642fu - (__float_as_uint(dsq) >> 1));
    r = r * fmaf(-0.5f * dsq * r, r, 1.5f);
    r = r * fmaf(-0.5f * dsq * r, r, 1.5f);
    return -(dsq * r);
}

// bf16 tensor-core GEMM: KS=64 -> 64 MMAs + 24 LDSMs per barrier (2x R7)
__global__ __launch_bounds__(256)
void gemm_bf16(float* __restrict__ dist) {
    extern __shared__ __nv_bfloat16 smem[];
    __nv_bfloat16* As = smem;                            // [NSTAGE][BM][LDA]
    __nv_bfloat16* Bs = smem + NSTAGE * BM * LDA;        // [NSTAGE][BN][LDA]

    int tid = threadIdx.x;
    int wid = tid >> 5, lane = tid & 31;
    int warp_m = wid >> 2, warp_n = wid & 3;             // 2 x 4 warps, warp tile 64x32
    int bm = blockIdx.y * BM, bn = blockIdx.x * BN;

    int lr = tid >> 3;                // row 0..31 (stride 32 rows per t-iter below)
    int ls = tid & 7;                 // 16B segment 0..7 within 64-elem row chunk
    const __nv_bfloat16* xg = g_xb + (size_t)bm * DIM;
    const __nv_bfloat16* eg = g_eb + (size_t)bn * DIM;

    float acc[4][4][4] = {};

    auto issue = [&](int kt, int s) {
        const __nv_bfloat16* xsrc = xg + kt * KS;
        const __nv_bfloat16* esrc = eg + kt * KS;
        __nv_bfloat16* Ad = As + (size_t)s * BM * LDA;
        __nv_bfloat16* Bd = Bs + (size_t)s * BN * LDA;
        #pragma unroll
        for (int t = 0; t < 4; t++) {
            int row = lr + t * 32;
            cp16(Ad + row * LDA + ls * 8, xsrc + (size_t)row * DIM + ls * 8);
            cp16(Bd + row * LDA + ls * 8, esrc + (size_t)row * DIM + ls * 8);
        }
    };

    issue(0, 0); CP_COMMIT();
    issue(1, 1); CP_COMMIT();

    int sc = 0, si = 2;
    #pragma unroll 1
    for (int kt = 0; kt < KT; kt++) {
        CP_WAIT1();
        __syncthreads();
        if (kt + NSTAGE - 1 < KT) issue(kt + NSTAGE - 1, si);
        CP_COMMIT();

        const __nv_bfloat16* Ab = As + (size_t)sc * BM * LDA;
        const __nv_bfloat16* Bb = Bs + (size_t)sc * BN * LDA;
        #pragma unroll
        for (int kk = 0; kk < 4; kk++) {
            unsigned a[4][4], b[4][2];
            #pragma unroll
            for (int mi = 0; mi < 4; mi++)
                ldsm_x4(a[mi][0], a[mi][1], a[mi][2], a[mi][3],
                        Ab + (warp_m * 64 + mi * 16 + (lane & 15)) * LDA
                           + kk * 16 + ((lane >> 4) << 3));
            #pragma unroll
            for (int nib = 0; nib < 2; nib++) {
                unsigned r0, r1, r2, r3;
                ldsm_x4(r0, r1, r2, r3,
                        Bb + (warp_n * 32 + nib * 16 + ((lane >> 4) << 3) + (lane & 7)) * LDA
                           + kk * 16 + (((lane >> 3) & 1) << 3));
                b[nib * 2][0] = r0; b[nib * 2][1] = r1;
                b[nib * 2 + 1][0] = r2; b[nib * 2 + 1][1] = r3;
            }
            #pragma unroll
            for (int mi = 0; mi < 4; mi++)
                #pragma unroll
                for (int ni = 0; ni < 4; ni++)
                    mma_bf16(acc[mi][ni], a[mi], b[ni]);
        }
        sc = (sc + 1 == NSTAGE) ? 0 : sc + 1;
        si = (si + 1 == NSTAGE) ? 0 : si + 1;
    }

    // epilogue (R7 structure): dist + per-row approx max
    int qr = lane >> 2, qc = 2 * (lane & 3);
    float x2v[4][2], rmax[4][2];
    #pragma unroll
    for (int mi = 0; mi < 4; mi++)
        #pragma unroll
        for (int h = 0; h < 2; h++) {
            x2v[mi][h] = g_x2[bm + warp_m * 64 + mi * 16 + h * 8 + qr];
            rmax[mi][h] = -1e30f;
        }

    #pragma unroll
    for (int ni = 0; ni < 4; ni++) {
        int n0 = bn + warp_n * 32 + ni * 8 + qc;
        float y0 = g_y2[n0], y1 = g_y2[n0 + 1];
        #pragma unroll
        for (int mi = 0; mi < 4; mi++)
            #pragma unroll
            for (int h = 0; h < 2; h++) {
                int rg = bm + warp_m * 64 + mi * 16 + h * 8 + qr;
                float d0 = negdist(x2v[mi][h], y0, acc[mi][ni][2 * h]);
                float d1 = negdist(x2v[mi][h], y1, acc[mi][ni][2 * h + 1]);
                *reinterpret_cast<float2*>(&dist[(size_t)rg * NCODE + n0]) = make_float2(d0, d1);
                rmax[mi][h] = fmaxf(rmax[mi][h], fmaxf(d0, d1));
            }
    }
    #pragma unroll
    for (int mi = 0; mi < 4; mi++)
        #pragma unroll
        for (int h = 0; h < 2; h++) {
            float v = rmax[mi][h];
            v = fmaxf(v, __shfl_xor_sync(0xffffffffu, v, 1));
            v = fmaxf(v, __shfl_xor_sync(0xffffffffu, v, 2));
            if ((lane & 3) == 0)
                atomicMax(&g_rowmax[bm + warp_m * 64 + mi * 16 + h * 8 + qr], fkey(v));
        }
}

// one warp per row: candidates within MARGIN of approx max, re-evaluated with the
// EXACT validated chain (sequential ascending-k fmaf + exact epilogue roundings).
#define RWARPS 8
__global__ __launch_bounds__(256)
void rescue(const float* __restrict__ x, const float* __restrict__ e,
            const float* __restrict__ dist) {
    __shared__ int s_cnt[RWARPS];
    __shared__ int s_cand[RWARPS][MAXCAND];

    int w = threadIdx.x >> 5, lane = threadIdx.x & 31;
    int row = blockIdx.x * RWARPS + w;

    if (lane == 0) s_cnt[w] = 0;
    __syncwarp();

    float thr = fkey_inv(g_rowmax[row]) - MARGIN;
    const float4* dp = reinterpret_cast<const float4*>(dist + (size_t)row * NCODE);
    for (int j = lane; j < NCODE / 4; j += 32) {
        float4 v = dp[j];
        #pragma unroll
        for (int q = 0; q < 4; q++) {
            float dv = (q == 0) ? v.x : (q == 1) ? v.y : (q == 2) ? v.z : v.w;
            if (dv >= thr) {
                int slot = atomicAdd(&s_cnt[w], 1);
                if (slot < MAXCAND) s_cand[w][slot] = 4 * j + q;
            }
        }
    }
    __syncwarp();
    int cnt = s_cnt[w];
    if (cnt > MAXCAND) cnt = MAXCAND;

    unsigned long long key = 0ull;
    if (lane < cnt) {
        int c = s_cand[w][lane];
        const float* xr = x + (size_t)row * DIM;
        const float* er = e + (size_t)c * DIM;
        float s = 0.0f;
        #pragma unroll 8
        for (int k = 0; k < DIM; k++)          // strictly ascending-k fp32 FMA chain
            s = fmaf(xr[k], er[k], s);
        float xyv = __fmul_rn(-2.0f, s);
        float t   = __fadd_rn(g_x2[row], g_y2[c]);
        float dsq = __fadd_rn(t, xyv);
        float dv  = -sqrtf(fmaxf(dsq, 0.0f));
        key = ((unsigned long long)fkey(dv) << 32) | (unsigned int)(NCODE - 1 - c);
    }
    #pragma unroll
    for (int off = 16; off > 0; off >>= 1) {
        unsigned long long o = __shfl_xor_sync(0xffffffffu, key, off);
        key = (o > key) ? o : key;
    }
    if (lane == 0)
        g_bestidx[row] = (NCODE - 1) - (int)(unsigned int)(key & 0xFFFFFFFFull);
}

__global__ void finalize(const float* __restrict__ embed,
                         float* __restrict__ out_q,
                         float* __restrict__ out_ind) {
    int row = blockIdx.x;
    int c = g_bestidx[row];
    if (threadIdx.x == 0) out_ind[row] = (float)c;
    const float4* src = reinterpret_cast<const float4*>(embed + (size_t)c * DIM);
    float4* dst = reinterpret_cast<float4*>(out_q + (size_t)row * DIM);
    for (int j = threadIdx.x; j < DIM / 4; j += blockDim.x) dst[j] = src[j];
}

extern "C" void kernel_launch(void* const* d_in, const int* in_sizes, int n_in,
                              void* d_out, int out_size) {
    const float* x = (const float*)d_in[0];      // [32768, 512]
    const float* e = (const float*)d_in[1];      // [8192, 512]
    float* out = (float*)d_out;

    float* out_q    = out;                                   // [N, D]
    float* out_ind  = out + (size_t)NROWS * DIM;             // [N]
    float* out_dist = out + (size_t)NROWS * DIM + NROWS;     // [N, C]

    float *d_x2, *d_y2;
    __nv_bfloat16 *d_xb, *d_eb;
    cudaGetSymbolAddress((void**)&d_x2, g_x2);
    cudaGetSymbolAddress((void**)&d_y2, g_y2);
    cudaGetSymbolAddress((void**)&d_xb, g_xb);
    cudaGetSymbolAddress((void**)&d_eb, g_eb);

    cudaFuncSetAttribute(gemm_bf16, cudaFuncAttributeMaxDynamicSharedMemorySize, SMEM_BYTES);

    init_scratch<<<(NROWS + 255) / 256, 256>>>();
    conv_norm<<<NROWS / 128, 128>>>(x, d_xb, d_x2, NROWS);
    conv_norm<<<NCODE / 128, 128>>>(e, d_eb, d_y2, NCODE);

    dim3 grid(NCODE / BN, NROWS / BM);
    gemm_bf16<<<grid, 256, SMEM_BYTES>>>(out_dist);

    rescue<<<NROWS / RWARPS, 256>>>(x, e, out_dist);

    finalize<<<NROWS, 128>>>(e, out_q, out_ind);
}

// round 12
// speedup vs baseline: 1.7220x; 1.0642x over previous
#include <cuda_runtime.h>
#include <cuda_bf16.h>
#include <math.h>

#define NROWS 32768
#define NCODE 8192
#define DIM   512

#define BM 128
#define BN 128
#define NCB (NCODE / BN)   // 64 column blocks
#define KS 64
#define KT (DIM / KS)      // 8
#define NSTAGE 3
#define LDA 72          // KS + 8 pad (bf16): 144B row stride -> conflict-free ldmatrix

#define MARGIN 0.02f
#define MAXCAND 32

#define SMEM_BYTES (NSTAGE * (BM + BN) * LDA * 2)   // 110592

// scratch (no allocations allowed)
__device__ float g_x2[NROWS];
__device__ float g_y2[NCODE];
__device__ unsigned int g_colmax[NROWS * NCB];   // fkey of per-(row, col-block) max
__device__ __nv_bfloat16 g_xb[NROWS * DIM];
__device__ __nv_bfloat16 g_eb[NCODE * DIM];

__device__ __forceinline__ unsigned int fkey(float v) {
    unsigned int b = __float_as_uint(v);
    return (b & 0x80000000u) ? ~b : (b | 0x80000000u);
}
__device__ __forceinline__ float fkey_inv(unsigned int k) {
    unsigned int b = (k & 0x80000000u) ? (k & 0x7FFFFFFFu) : ~k;
    return __uint_as_float(b);
}

__global__ void init_scratch() {
    int i = blockIdx.x * blockDim.x + threadIdx.x;
    if (i < NROWS * NCB) g_colmax[i] = 0u;
}

// FUSED: bf16 convert + strictly sequential scalar fp32 norm (bit-matches
// XLA-CPU reduce; identical op order to the VALIDATED R5-R11 chain).
__global__ __launch_bounds__(128)
void conv_norm(const float* __restrict__ m, __nv_bfloat16* __restrict__ d,
               float* __restrict__ out, int rows) {
    int row = blockIdx.x * blockDim.x + threadIdx.x;
    if (row >= rows) return;
    const float4* p = reinterpret_cast<const float4*>(m + (size_t)row * DIM);
    __nv_bfloat162* q = reinterpret_cast<__nv_bfloat162*>(d + (size_t)row * DIM);
    float s = 0.0f;
    #pragma unroll 4
    for (int j = 0; j < DIM / 4; j++) {
        float4 v = p[j];
        s = __fadd_rn(s, __fmul_rn(v.x, v.x));
        s = __fadd_rn(s, __fmul_rn(v.y, v.y));
        s = __fadd_rn(s, __fmul_rn(v.z, v.z));
        s = __fadd_rn(s, __fmul_rn(v.w, v.w));
        q[2 * j]     = __floats2bfloat162_rn(v.x, v.y);
        q[2 * j + 1] = __floats2bfloat162_rn(v.z, v.w);
    }
    out[row] = s;
}

__device__ __forceinline__ void ldsm_x4(unsigned& r0, unsigned& r1, unsigned& r2, unsigned& r3,
                                        const void* ptr) {
    unsigned addr = (unsigned)__cvta_generic_to_shared(ptr);
    asm volatile("ldmatrix.sync.aligned.m8n8.x4.shared.b16 {%0,%1,%2,%3}, [%4];"
                 : "=r"(r0), "=r"(r1), "=r"(r2), "=r"(r3) : "r"(addr));
}
__device__ __forceinline__ void mma_bf16(float* c, const unsigned* a, const unsigned* b) {
    asm volatile(
        "mma.sync.aligned.m16n8k16.row.col.f32.bf16.bf16.f32 "
        "{%0,%1,%2,%3}, {%4,%5,%6,%7}, {%8,%9}, {%0,%1,%2,%3};"
        : "+f"(c[0]), "+f"(c[1]), "+f"(c[2]), "+f"(c[3])
        : "r"(a[0]), "r"(a[1]), "r"(a[2]), "r"(a[3]), "r"(b[0]), "r"(b[1]));
}
__device__ __forceinline__ void cp16(void* dst, const void* src) {
    unsigned d = (unsigned)__cvta_generic_to_shared(dst);
    asm volatile("cp.async.cg.shared.global [%0], [%1], 16;" :: "r"(d), "l"(src));
}
#define CP_COMMIT() asm volatile("cp.async.commit_group;")
#define CP_WAIT1()  asm volatile("cp.async.wait_group 1;")

// fast sqrt on the FMA pipe (no MUFU): rsqrt bit-hack + 2 Newton, ~4e-6 rel.
// Only feeds the dist output (tolerance 1e-3) and the candidate pre-filter
// (MARGIN 0.02 >> error); the rescue exact chain never sees it.
__device__ __forceinline__ float negdist(float x2, float y2, float sxy) {
    float dsq = __fadd_rn(__fadd_rn(x2, y2), __fmul_rn(-2.0f, sxy));
    dsq = fmaxf(dsq, 1e-12f);
    float r = __uint_as_float(0x5f37642fu - (__float_as_uint(dsq) >> 1));
    r = r * fmaf(-0.5f * dsq * r, r, 1.5f);
    r = r * fmaf(-0.5f * dsq * r, r, 1.5f);
    return -(dsq * r);
}

// bf16 tensor-core GEMM (VALIDATED R11 mainloop): KS=64 -> 64 MMAs/barrier
__global__ __launch_bounds__(256)
void gemm_bf16(float* __restrict__ dist) {
    extern __shared__ __nv_bfloat16 smem[];
    __nv_bfloat16* As = smem;                            // [NSTAGE][BM][LDA]
    __nv_bfloat16* Bs = smem + NSTAGE * BM * LDA;        // [NSTAGE][BN][LDA]

    int tid = threadIdx.x;
    int wid = tid >> 5, lane = tid & 31;
    int warp_m = wid >> 2, warp_n = wid & 3;             // 2 x 4 warps, warp tile 64x32
    int bm = blockIdx.y * BM, bn = blockIdx.x * BN;

    int lr = tid >> 3;                // row 0..31 (stride 32 rows per t-iter below)
    int ls = tid & 7;                 // 16B segment 0..7 within 64-elem row chunk
    const __nv_bfloat16* xg = g_xb + (size_t)bm * DIM;
    const __nv_bfloat16* eg = g_eb + (size_t)bn * DIM;

    float acc[4][4][4] = {};

    auto issue = [&](int kt, int s) {
        const __nv_bfloat16* xsrc = xg + kt * KS;
        const __nv_bfloat16* esrc = eg + kt * KS;
        __nv_bfloat16* Ad = As + (size_t)s * BM * LDA;
        __nv_bfloat16* Bd = Bs + (size_t)s * BN * LDA;
        #pragma unroll
        for (int t = 0; t < 4; t++) {
            int row = lr + t * 32;
            cp16(Ad + row * LDA + ls * 8, xsrc + (size_t)row * DIM + ls * 8);
            cp16(Bd + row * LDA + ls * 8, esrc + (size_t)row * DIM + ls * 8);
        }
    };

    issue(0, 0); CP_COMMIT();
    issue(1, 1); CP_COMMIT();

    int sc = 0, si = 2;
    #pragma unroll 1
    for (int kt = 0; kt < KT; kt++) {
        CP_WAIT1();
        __syncthreads();
        if (kt + NSTAGE - 1 < KT) issue(kt + NSTAGE - 1, si);
        CP_COMMIT();

        const __nv_bfloat16* Ab = As + (size_t)sc * BM * LDA;
        const __nv_bfloat16* Bb = Bs + (size_t)sc * BN * LDA;
        #pragma unroll
        for (int kk = 0; kk < 4; kk++) {
            unsigned a[4][4], b[4][2];
            #pragma unroll
            for (int mi = 0; mi < 4; mi++)
                ldsm_x4(a[mi][0], a[mi][1], a[mi][2], a[mi][3],
                        Ab + (warp_m * 64 + mi * 16 + (lane & 15)) * LDA
                           + kk * 16 + ((lane >> 4) << 3));
            #pragma unroll
            for (int nib = 0; nib < 2; nib++) {
                unsigned r0, r1, r2, r3;
                ldsm_x4(r0, r1, r2, r3,
                        Bb + (warp_n * 32 + nib * 16 + ((lane >> 4) << 3) + (lane & 7)) * LDA
                           + kk * 16 + (((lane >> 3) & 1) << 3));
                b[nib * 2][0] = r0; b[nib * 2][1] = r1;
                b[nib * 2 + 1][0] = r2; b[nib * 2 + 1][1] = r3;
            }
            #pragma unroll
            for (int mi = 0; mi < 4; mi++)
                #pragma unroll
                for (int ni = 0; ni < 4; ni++)
                    mma_bf16(acc[mi][ni], a[mi], b[ni]);
        }
        sc = (sc + 1 == NSTAGE) ? 0 : sc + 1;
        si = (si + 1 == NSTAGE) ? 0 : si + 1;
    }

    // epilogue: dist + per-(row, col-block) max into g_colmax
    int qr = lane >> 2, qc = 2 * (lane & 3);
    float x2v[4][2], rmax[4][2];
    #pragma unroll
    for (int mi = 0; mi < 4; mi++)
        #pragma unroll
        for (int h = 0; h < 2; h++) {
            x2v[mi][h] = g_x2[bm + warp_m * 64 + mi * 16 + h * 8 + qr];
            rmax[mi][h] = -1e30f;
        }

    #pragma unroll
    for (int ni = 0; ni < 4; ni++) {
        int n0 = bn + warp_n * 32 + ni * 8 + qc;
        float y0 = g_y2[n0], y1 = g_y2[n0 + 1];
        #pragma unroll
        for (int mi = 0; mi < 4; mi++)
            #pragma unroll
            for (int h = 0; h < 2; h++) {
                int rg = bm + warp_m * 64 + mi * 16 + h * 8 + qr;
                float d0 = negdist(x2v[mi][h], y0, acc[mi][ni][2 * h]);
                float d1 = negdist(x2v[mi][h], y1, acc[mi][ni][2 * h + 1]);
                *reinterpret_cast<float2*>(&dist[(size_t)rg * NCODE + n0]) = make_float2(d0, d1);
                rmax[mi][h] = fmaxf(rmax[mi][h], fmaxf(d0, d1));
            }
    }
    #pragma unroll
    for (int mi = 0; mi < 4; mi++)
        #pragma unroll
        for (int h = 0; h < 2; h++) {
            float v = rmax[mi][h];
            v = fmaxf(v, __shfl_xor_sync(0xffffffffu, v, 1));
            v = fmaxf(v, __shfl_xor_sync(0xffffffffu, v, 2));
            if ((lane & 3) == 0) {
                int rg = bm + warp_m * 64 + mi * 16 + h * 8 + qr;
                atomicMax(&g_colmax[rg * NCB + blockIdx.x], fkey(v));
            }
        }
}

// one warp per row: find approx row max from the 64 block maxima, scan ONLY
// qualifying blocks for candidates, re-evaluate with the EXACT validated chain
// (sequential ascending-k fmaf + exact epilogue roundings), then write
// out_ind and gather the embed row into out_q (finalize fused).
#define RWARPS 8
__global__ __launch_bounds__(256)
void rescue(const float* __restrict__ x, const float* __restrict__ e,
            const float* __restrict__ dist,
            float* __restrict__ out_q, float* __restrict__ out_ind) {
    __shared__ int s_cnt[RWARPS];
    __shared__ int s_cand[RWARPS][MAXCAND];

    int w = threadIdx.x >> 5, lane = threadIdx.x & 31;
    int row = blockIdx.x * RWARPS + w;

    if (lane == 0) s_cnt[w] = 0;
    __syncwarp();

    // block maxima: lane holds blocks lane and lane+32
    float cm0 = fkey_inv(g_colmax[row * NCB + lane]);
    float cm1 = fkey_inv(g_colmax[row * NCB + 32 + lane]);
    float m = fmaxf(cm0, cm1);
    #pragma unroll
    for (int off = 16; off > 0; off >>= 1)
        m = fmaxf(m, __shfl_xor_sync(0xffffffffu, m, off));
    float thr = m - MARGIN;

    // scan only qualifying blocks (expected ~1)
    const float* dp = dist + (size_t)row * NCODE;
    #pragma unroll 1
    for (int b = 0; b < NCB; b++) {
        float cb = (b < 32) ? __shfl_sync(0xffffffffu, cm0, b)
                            : __shfl_sync(0xffffffffu, cm1, b - 32);
        if (cb >= thr) {
            float4 v = *reinterpret_cast<const float4*>(dp + b * BN + lane * 4);
            #pragma unroll
            for (int q = 0; q < 4; q++) {
                float dv = (q == 0) ? v.x : (q == 1) ? v.y : (q == 2) ? v.z : v.w;
                if (dv >= thr) {
                    int slot = atomicAdd(&s_cnt[w], 1);
                    if (slot < MAXCAND) s_cand[w][slot] = b * BN + lane * 4 + q;
                }
            }
        }
    }
    __syncwarp();
    int cnt = s_cnt[w];
    if (cnt > MAXCAND) cnt = MAXCAND;

    unsigned long long key = 0ull;
    if (lane < cnt) {
        int c = s_cand[w][lane];
        const float* xr = x + (size_t)row * DIM;
        const float* er = e + (size_t)c * DIM;
        float s = 0.0f;
        #pragma unroll 8
        for (int k = 0; k < DIM; k++)          // strictly ascending-k fp32 FMA chain
            s = fmaf(xr[k], er[k], s);
        float xyv = __fmul_rn(-2.0f, s);
        float t   = __fadd_rn(g_x2[row], g_y2[c]);
        float dsq = __fadd_rn(t, xyv);
        float dv  = -sqrtf(fmaxf(dsq, 0.0f));
        key = ((unsigned long long)fkey(dv) << 32) | (unsigned int)(NCODE - 1 - c);
    }
    #pragma unroll
    for (int off = 16; off > 0; off >>= 1) {
        unsigned long long o = __shfl_xor_sync(0xffffffffu, key, off);
        key = (o > key) ? o : key;
    }
    int best = (NCODE - 1) - (int)(unsigned int)(__shfl_sync(0xffffffffu, key, 0) & 0xFFFFFFFFull);

    // fused finalize: index + gather
    if (lane == 0) out_ind[row] = (float)best;
    const float4* src = reinterpret_cast<const float4*>(e + (size_t)best * DIM);
    float4* dst = reinterpret_cast<float4*>(out_q + (size_t)row * DIM);
    #pragma unroll
    for (int j = 0; j < DIM / 4 / 32; j++)
        dst[lane + 32 * j] = src[lane + 32 * j];
}

extern "C" void kernel_launch(void* const* d_in, const int* in_sizes, int n_in,
                              void* d_out, int out_size) {
    const float* x = (const float*)d_in[0];      // [32768, 512]
    const float* e = (const float*)d_in[1];      // [8192, 512]
    float* out = (float*)d_out;

    float* out_q    = out;                                   // [N, D]
    float* out_ind  = out + (size_t)NROWS * DIM;             // [N]
    float* out_dist = out + (size_t)NROWS * DIM + NROWS;     // [N, C]

    float *d_x2, *d_y2;
    __nv_bfloat16 *d_xb, *d_eb;
    cudaGetSymbolAddress((void**)&d_x2, g_x2);
    cudaGetSymbolAddress((void**)&d_y2, g_y2);
    cudaGetSymbolAddress((void**)&d_xb, g_xb);
    cudaGetSymbolAddress((void**)&d_eb, g_eb);

    cudaFuncSetAttribute(gemm_bf16, cudaFuncAttributeMaxDynamicSharedMemorySize, SMEM_BYTES);

    init_scratch<<<(NROWS * NCB + 255) / 256, 256>>>();
    conv_norm<<<NROWS / 128, 128>>>(x, d_xb, d_x2, NROWS);
    conv_norm<<<NCODE / 128, 128>>>(e, d_eb, d_y2, NCODE);

    dim3 grid(NCODE / BN, NROWS / BM);
    gemm_bf16<<<grid, 256, SMEM_BYTES>>>(out_dist);

    rescue<<<NROWS / RWARPS, 256>>>(x, e, out_dist, out_q, out_ind);
}

// round 13
// speedup vs baseline: 1.7603x; 1.0222x over previous
#include <cuda_runtime.h>
#include <cuda_bf16.h>
#include <math.h>

#define NROWS 32768
#define NCODE 8192
#define DIM   512

#define BM 128
#define BN 128
#define NCB (NCODE / BN)   // 64 column blocks
#define KS 64
#define KT (DIM / KS)      // 8
#define NSTAGE 3
#define LDA 72          // KS + 8 pad (bf16): 144B row stride -> conflict-free ldmatrix

#define MARGIN 0.02f
#define MAXCAND 32

#define SMEM_BYTES (NSTAGE * (BM + BN) * LDA * 2)   // 110592

// scratch (no allocations allowed)
__device__ float g_x2[NROWS];
__device__ float g_y2[NCODE];
__device__ unsigned int g_colmax[NROWS * NCB];   // fkey of per-(row, col-block) max
__device__ __nv_bfloat16 g_xb[NROWS * DIM];
__device__ __nv_bfloat16 g_eb[NCODE * DIM];

__device__ __forceinline__ unsigned int fkey(float v) {
    unsigned int b = __float_as_uint(v);
    return (b & 0x80000000u) ? ~b : (b | 0x80000000u);
}
__device__ __forceinline__ float fkey_inv(unsigned int k) {
    unsigned int b = (k & 0x80000000u) ? (k & 0x7FFFFFFFu) : ~k;
    return __uint_as_float(b);
}

// FUSED over x and e: bf16 convert + strictly sequential scalar fp32 norm
// (bit-matches XLA-CPU reduce; identical op order to the VALIDATED R5-R12 chain).
__global__ __launch_bounds__(128)
void conv_norm_all(const float* __restrict__ x, const float* __restrict__ e) {
    int idx = blockIdx.x * blockDim.x + threadIdx.x;
    const float* src;
    __nv_bfloat16* dst;
    float* outp;
    if (idx < NROWS) {
        src = x + (size_t)idx * DIM;
        dst = g_xb + (size_t)idx * DIM;
        outp = &g_x2[idx];
    } else if (idx < NROWS + NCODE) {
        int r = idx - NROWS;
        src = e + (size_t)r * DIM;
        dst = g_eb + (size_t)r * DIM;
        outp = &g_y2[r];
    } else return;

    const float4* p = reinterpret_cast<const float4*>(src);
    __nv_bfloat162* q = reinterpret_cast<__nv_bfloat162*>(dst);
    float s = 0.0f;
    #pragma unroll 4
    for (int j = 0; j < DIM / 4; j++) {
        float4 v = p[j];
        s = __fadd_rn(s, __fmul_rn(v.x, v.x));
        s = __fadd_rn(s, __fmul_rn(v.y, v.y));
        s = __fadd_rn(s, __fmul_rn(v.z, v.z));
        s = __fadd_rn(s, __fmul_rn(v.w, v.w));
        q[2 * j]     = __floats2bfloat162_rn(v.x, v.y);
        q[2 * j + 1] = __floats2bfloat162_rn(v.z, v.w);
    }
    *outp = s;
}

__device__ __forceinline__ void ldsm_x4(unsigned& r0, unsigned& r1, unsigned& r2, unsigned& r3,
                                        const void* ptr) {
    unsigned addr = (unsigned)__cvta_generic_to_shared(ptr);
    asm volatile("ldmatrix.sync.aligned.m8n8.x4.shared.b16 {%0,%1,%2,%3}, [%4];"
                 : "=r"(r0), "=r"(r1), "=r"(r2), "=r"(r3) : "r"(addr));
}
__device__ __forceinline__ void mma_bf16(float* c, const unsigned* a, const unsigned* b) {
    asm volatile(
        "mma.sync.aligned.m16n8k16.row.col.f32.bf16.bf16.f32 "
        "{%0,%1,%2,%3}, {%4,%5,%6,%7}, {%8,%9}, {%0,%1,%2,%3};"
        : "+f"(c[0]), "+f"(c[1]), "+f"(c[2]), "+f"(c[3])
        : "r"(a[0]), "r"(a[1]), "r"(a[2]), "r"(a[3]), "r"(b[0]), "r"(b[1]));
}
__device__ __forceinline__ void cp16(void* dst, const void* src) {
    unsigned d = (unsigned)__cvta_generic_to_shared(dst);
    asm volatile("cp.async.cg.shared.global [%0], [%1], 16;" :: "r"(d), "l"(src));
}
#define CP_COMMIT() asm volatile("cp.async.commit_group;")
#define CP_WAIT1()  asm volatile("cp.async.wait_group 1;")

// fast sqrt on the FMA pipe (no MUFU): rsqrt bit-hack + 2 Newton, ~4e-6 rel.
// Only feeds the dist output (tolerance 1e-3) and the candidate pre-filter
// (MARGIN 0.02 >> error); the rescue exact chain never sees it.
__device__ __forceinline__ float negdist(float x2, float y2, float sxy) {
    float dsq = __fadd_rn(__fadd_rn(x2, y2), __fmul_rn(-2.0f, sxy));
    dsq = fmaxf(dsq, 1e-12f);
    float r = __uint_as_float(0x5f37642fu - (__float_as_uint(dsq) >> 1));
    r = r * fmaf(-0.5f * dsq * r, r, 1.5f);
    r = r * fmaf(-0.5f * dsq * r, r, 1.5f);
    return -(dsq * r);
}

// bf16 tensor-core GEMM (VALIDATED R11/R12 mainloop): KS=64 -> 64 MMAs/barrier
__global__ __launch_bounds__(256)
void gemm_bf16(float* __restrict__ dist) {
    extern __shared__ __nv_bfloat16 smem[];
    __nv_bfloat16* As = smem;                            // [NSTAGE][BM][LDA]
    __nv_bfloat16* Bs = smem + NSTAGE * BM * LDA;        // [NSTAGE][BN][LDA]

    int tid = threadIdx.x;
    int wid = tid >> 5, lane = tid & 31;
    int warp_m = wid >> 2, warp_n = wid & 3;             // 2 x 4 warps, warp tile 64x32
    int bm = blockIdx.y * BM, bn = blockIdx.x * BN;

    int lr = tid >> 3;                // row 0..31 (stride 32 rows per t-iter below)
    int ls = tid & 7;                 // 16B segment 0..7 within 64-elem row chunk
    const __nv_bfloat16* xg = g_xb + (size_t)bm * DIM;
    const __nv_bfloat16* eg = g_eb + (size_t)bn * DIM;

    float acc[4][4][4] = {};

    auto issue = [&](int kt, int s) {
        const __nv_bfloat16* xsrc = xg + kt * KS;
        const __nv_bfloat16* esrc = eg + kt * KS;
        __nv_bfloat16* Ad = As + (size_t)s * BM * LDA;
        __nv_bfloat16* Bd = Bs + (size_t)s * BN * LDA;
        #pragma unroll
        for (int t = 0; t < 4; t++) {
            int row = lr + t * 32;
            cp16(Ad + row * LDA + ls * 8, xsrc + (size_t)row * DIM + ls * 8);
            cp16(Bd + row * LDA + ls * 8, esrc + (size_t)row * DIM + ls * 8);
        }
    };

    issue(0, 0); CP_COMMIT();
    issue(1, 1); CP_COMMIT();

    int sc = 0, si = 2;
    #pragma unroll 1
    for (int kt = 0; kt < KT; kt++) {
        CP_WAIT1();
        __syncthreads();
        if (kt + NSTAGE - 1 < KT) issue(kt + NSTAGE - 1, si);
        CP_COMMIT();

        const __nv_bfloat16* Ab = As + (size_t)sc * BM * LDA;
        const __nv_bfloat16* Bb = Bs + (size_t)sc * BN * LDA;
        #pragma unroll
        for (int kk = 0; kk < 4; kk++) {
            unsigned a[4][4], b[4][2];
            #pragma unroll
            for (int mi = 0; mi < 4; mi++)
                ldsm_x4(a[mi][0], a[mi][1], a[mi][2], a[mi][3],
                        Ab + (warp_m * 64 + mi * 16 + (lane & 15)) * LDA
                           + kk * 16 + ((lane >> 4) << 3));
            #pragma unroll
            for (int nib = 0; nib < 2; nib++) {
                unsigned r0, r1, r2, r3;
                ldsm_x4(r0, r1, r2, r3,
                        Bb + (warp_n * 32 + nib * 16 + ((lane >> 4) << 3) + (lane & 7)) * LDA
                           + kk * 16 + (((lane >> 3) & 1) << 3));
                b[nib * 2][0] = r0; b[nib * 2][1] = r1;
                b[nib * 2 + 1][0] = r2; b[nib * 2 + 1][1] = r3;
            }
            #pragma unroll
            for (int mi = 0; mi < 4; mi++)
                #pragma unroll
                for (int ni = 0; ni < 4; ni++)
                    mma_bf16(acc[mi][ni], a[mi], b[ni]);
        }
        sc = (sc + 1 == NSTAGE) ? 0 : sc + 1;
        si = (si + 1 == NSTAGE) ? 0 : si + 1;
    }

    // epilogue: dist (streaming stores) + per-(row, col-block) max via smem
    int qr = lane >> 2, qc = 2 * (lane & 3);
    float x2v[4][2], rmax[4][2];
    #pragma unroll
    for (int mi = 0; mi < 4; mi++)
        #pragma unroll
        for (int h = 0; h < 2; h++) {
            x2v[mi][h] = g_x2[bm + warp_m * 64 + mi * 16 + h * 8 + qr];
            rmax[mi][h] = -1e30f;
        }

    #pragma unroll
    for (int ni = 0; ni < 4; ni++) {
        int n0 = bn + warp_n * 32 + ni * 8 + qc;
        float y0 = g_y2[n0], y1 = g_y2[n0 + 1];
        #pragma unroll
        for (int mi = 0; mi < 4; mi++)
            #pragma unroll
            for (int h = 0; h < 2; h++) {
                int rg = bm + warp_m * 64 + mi * 16 + h * 8 + qr;
                float d0 = negdist(x2v[mi][h], y0, acc[mi][ni][2 * h]);
                float d1 = negdist(x2v[mi][h], y1, acc[mi][ni][2 * h + 1]);
                __stcs(reinterpret_cast<float2*>(&dist[(size_t)rg * NCODE + n0]),
                       make_float2(d0, d1));
                rmax[mi][h] = fmaxf(rmax[mi][h], fmaxf(d0, d1));
            }
    }

    // smem reduction across the 4 warp_n warps (no atomics, no init kernel).
    // Tiles are no longer needed; barrier then reuse smem.
    float* s_rm = reinterpret_cast<float*>(smem);    // [4][BM] = 2KB
    __syncthreads();
    #pragma unroll
    for (int mi = 0; mi < 4; mi++)
        #pragma unroll
        for (int h = 0; h < 2; h++) {
            float v = rmax[mi][h];
            v = fmaxf(v, __shfl_xor_sync(0xffffffffu, v, 1));
            v = fmaxf(v, __shfl_xor_sync(0xffffffffu, v, 2));
            if ((lane & 3) == 0)
                s_rm[warp_n * BM + warp_m * 64 + mi * 16 + h * 8 + qr] = v;
        }
    __syncthreads();
    if (tid < BM) {
        float v = fmaxf(fmaxf(s_rm[tid], s_rm[BM + tid]),
                        fmaxf(s_rm[2 * BM + tid], s_rm[3 * BM + tid]));
        g_colmax[(size_t)(bm + tid) * NCB + blockIdx.x] = fkey(v);
    }
}

// one warp per row: approx row max from the 64 block maxima, scan ONLY
// qualifying blocks, re-evaluate with the EXACT validated chain
// (sequential ascending-k fmaf + exact epilogue roundings), write out_ind,
// gather embed row into out_q (finalize fused).
#define RWARPS 8
__global__ __launch_bounds__(256)
void rescue(const float* __restrict__ x, const float* __restrict__ e,
            const float* __restrict__ dist,
            float* __restrict__ out_q, float* __restrict__ out_ind) {
    __shared__ int s_cnt[RWARPS];
    __shared__ int s_cand[RWARPS][MAXCAND];

    int w = threadIdx.x >> 5, lane = threadIdx.x & 31;
    int row = blockIdx.x * RWARPS + w;

    if (lane == 0) s_cnt[w] = 0;
    __syncwarp();

    // block maxima: lane holds blocks lane and lane+32
    float cm0 = fkey_inv(g_colmax[(size_t)row * NCB + lane]);
    float cm1 = fkey_inv(g_colmax[(size_t)row * NCB + 32 + lane]);
    float m = fmaxf(cm0, cm1);
    #pragma unroll
    for (int off = 16; off > 0; off >>= 1)
        m = fmaxf(m, __shfl_xor_sync(0xffffffffu, m, off));
    float thr = m - MARGIN;

    // scan only qualifying blocks (expected ~1)
    const float* dp = dist + (size_t)row * NCODE;
    #pragma unroll 1
    for (int b = 0; b < NCB; b++) {
        float cb = (b < 32) ? __shfl_sync(0xffffffffu, cm0, b)
                            : __shfl_sync(0xffffffffu, cm1, b - 32);
        if (cb >= thr) {
            float4 v = *reinterpret_cast<const float4*>(dp + b * BN + lane * 4);
            #pragma unroll
            for (int q = 0; q < 4; q++) {
                float dv = (q == 0) ? v.x : (q == 1) ? v.y : (q == 2) ? v.z : v.w;
                if (dv >= thr) {
                    int slot = atomicAdd(&s_cnt[w], 1);
                    if (slot < MAXCAND) s_cand[w][slot] = b * BN + lane * 4 + q;
                }
            }
        }
    }
    __syncwarp();
    int cnt = s_cnt[w];
    if (cnt > MAXCAND) cnt = MAXCAND;

    unsigned long long key = 0ull;
    if (lane < cnt) {
        int c = s_cand[w][lane];
        const float* xr = x + (size_t)row * DIM;
        const float* er = e + (size_t)c * DIM;
        float s = 0.0f;
        #pragma unroll 8
        for (int k = 0; k < DIM; k++)          // strictly ascending-k fp32 FMA chain
            s = fmaf(xr[k], er[k], s);
        float xyv = __fmul_rn(-2.0f, s);
        float t   = __fadd_rn(g_x2[row], g_y2[c]);
        float dsq = __fadd_rn(t, xyv);
        float dv  = -sqrtf(fmaxf(dsq, 0.0f));
        key = ((unsigned long long)fkey(dv) << 32) | (unsigned int)(NCODE - 1 - c);
    }
    #pragma unroll
    for (int off = 16; off > 0; off >>= 1) {
        unsigned long long o = __shfl_xor_sync(0xffffffffu, key, off);
        key = (o > key) ? o : key;
    }
    int best = (NCODE - 1) - (int)(unsigned int)(__shfl_sync(0xffffffffu, key, 0) & 0xFFFFFFFFull);

    // fused finalize: index + gather (streaming writes)
    if (lane == 0) out_ind[row] = (float)best;
    const float4* src = reinterpret_cast<const float4*>(e + (size_t)best * DIM);
    float4* dst = reinterpret_cast<float4*>(out_q + (size_t)row * DIM);
    #pragma unroll
    for (int j = 0; j < DIM / 4 / 32; j++)
        __stcs(&dst[lane + 32 * j], src[lane + 32 * j]);
}

extern "C" void kernel_launch(void* const* d_in, const int* in_sizes, int n_in,
                              void* d_out, int out_size) {
    const float* x = (const float*)d_in[0];      // [32768, 512]
    const float* e = (const float*)d_in[1];      // [8192, 512]
    float* out = (float*)d_out;

    float* out_q    = out;                                   // [N, D]
    float* out_ind  = out + (size_t)NROWS * DIM;             // [N]
    float* out_dist = out + (size_t)NROWS * DIM + NROWS;     // [N, C]

    cudaFuncSetAttribute(gemm_bf16, cudaFuncAttributeMaxDynamicSharedMemorySize, SMEM_BYTES);

    conv_norm_all<<<(NROWS + NCODE) / 128, 128>>>(x, e);

    dim3 grid(NCODE / BN, NROWS / BM);
    gemm_bf16<<<grid, 256, SMEM_BYTES>>>(out_dist);

    rescue<<<NROWS / RWARPS, 256>>>(x, e, out_dist, out_q, out_ind);
}

// round 14
// speedup vs baseline: 1.8261x; 1.0374x over previous
#include <cuda_runtime.h>
#include <cuda_bf16.h>
#include <math.h>

#define NROWS 32768
#define NCODE 8192
#define DIM   512

#define BM 128
#define BN 128
#define NCB (NCODE / BN)   // 64 column blocks
#define KS 64
#define KT (DIM / KS)      // 8
#define NSTAGE 3
#define LDA 72          // KS + 8 pad (bf16): 144B row stride -> conflict-free ldmatrix

#define MARGIN 0.02f
#define MAXCAND 32

#define SMEM_BYTES (NSTAGE * (BM + BN) * LDA * 2)   // 110592

// scratch (no allocations allowed)
__device__ float g_x2[NROWS];
__device__ float g_y2[NCODE];
__device__ unsigned int g_colmax[NROWS * NCB];   // fkey of per-(row, col-block) max
__device__ __nv_bfloat16 g_xb[NROWS * DIM];
__device__ __nv_bfloat16 g_eb[NCODE * DIM];

__device__ __forceinline__ unsigned int fkey(float v) {
    unsigned int b = __float_as_uint(v);
    return (b & 0x80000000u) ? ~b : (b | 0x80000000u);
}
__device__ __forceinline__ float fkey_inv(unsigned int k) {
    unsigned int b = (k & 0x80000000u) ? (k & 0x7FFFFFFFu) : ~k;
    return __uint_as_float(b);
}

// FUSED bf16 convert + strictly sequential scalar fp32 norm, smem-staged for
// coalescing. Chunks are processed in ascending k order and within each chunk
// the per-row accumulation is the same __fadd_rn(s, __fmul_rn(v,v)) ascending
// chain as R5-R13 -> the norm value is BITWISE IDENTICAL to the validated one.
// Block = 128 threads = 128 rows; 8 chunks of 64 columns.
__global__ __launch_bounds__(128)
void conv_norm_all(const float* __restrict__ x, const float* __restrict__ e) {
    __shared__ float sb[128][65];      // stride 65 -> conflict-free column reads

    int t = threadIdx.x;
    int blk = blockIdx.x;              // 0..255 -> x rows, 256..319 -> e rows
    const float* src;
    __nv_bfloat16* dst;
    float* outp;
    int row0;
    if (blk < NROWS / 128) {
        row0 = blk * 128;
        src = x + (size_t)row0 * DIM;
        dst = g_xb + (size_t)row0 * DIM;
        outp = g_x2 + row0;
    } else {
        row0 = (blk - NROWS / 128) * 128;
        src = e + (size_t)row0 * DIM;
        dst = g_eb + (size_t)row0 * DIM;
        outp = g_y2 + row0;
    }

    float s = 0.0f;
    #pragma unroll 1
    for (int c = 0; c < 8; c++) {               // 8 chunks of 64 columns, ascending
        // coalesced load: 128 rows x 16 float4 (warp covers 2 rows x 256B)
        #pragma unroll
        for (int i = 0; i < 16; i++) {
            int id = t + i * 128;
            int r = id >> 4, sg = id & 15;
            float4 v = *reinterpret_cast<const float4*>(
                src + (size_t)r * DIM + c * 64 + sg * 4);
            sb[r][sg * 4 + 0] = v.x; sb[r][sg * 4 + 1] = v.y;
            sb[r][sg * 4 + 2] = v.z; sb[r][sg * 4 + 3] = v.w;
        }
        __syncthreads();

        // strictly sequential fp32 chain on own row (ascending k)
        #pragma unroll 8
        for (int k = 0; k < 64; k++) {
            float v = sb[t][k];
            s = __fadd_rn(s, __fmul_rn(v, v));
        }

        // cooperative coalesced bf16 store: warp writes one row's 128B chunk
        #pragma unroll
        for (int i = 0; i < 32; i++) {
            int id = t + i * 128;
            int r = id >> 5, sg = id & 31;
            __nv_bfloat162 pr = __floats2bfloat162_rn(sb[r][sg * 2], sb[r][sg * 2 + 1]);
            *reinterpret_cast<__nv_bfloat162*>(
                dst + (size_t)r * DIM + c * 64 + sg * 2) = pr;
        }
        __syncthreads();
    }
    outp[t] = s;
}

__device__ __forceinline__ void ldsm_x4(unsigned& r0, unsigned& r1, unsigned& r2, unsigned& r3,
                                        const void* ptr) {
    unsigned addr = (unsigned)__cvta_generic_to_shared(ptr);
    asm volatile("ldmatrix.sync.aligned.m8n8.x4.shared.b16 {%0,%1,%2,%3}, [%4];"
                 : "=r"(r0), "=r"(r1), "=r"(r2), "=r"(r3) : "r"(addr));
}
__device__ __forceinline__ void mma_bf16(float* c, const unsigned* a, const unsigned* b) {
    asm volatile(
        "mma.sync.aligned.m16n8k16.row.col.f32.bf16.bf16.f32 "
        "{%0,%1,%2,%3}, {%4,%5,%6,%7}, {%8,%9}, {%0,%1,%2,%3};"
        : "+f"(c[0]), "+f"(c[1]), "+f"(c[2]), "+f"(c[3])
        : "r"(a[0]), "r"(a[1]), "r"(a[2]), "r"(a[3]), "r"(b[0]), "r"(b[1]));
}
__device__ __forceinline__ void cp16(void* dst, const void* src) {
    unsigned d = (unsigned)__cvta_generic_to_shared(dst);
    asm volatile("cp.async.cg.shared.global [%0], [%1], 16;" :: "r"(d), "l"(src));
}
#define CP_COMMIT() asm volatile("cp.async.commit_group;")
#define CP_WAIT1()  asm volatile("cp.async.wait_group 1;")

// fast sqrt on the FMA pipe (no MUFU): rsqrt bit-hack + 2 Newton, ~4e-6 rel.
__device__ __forceinline__ float negdist(float x2, float y2, float sxy) {
    float dsq = __fadd_rn(__fadd_rn(x2, y2), __fmul_rn(-2.0f, sxy));
    dsq = fmaxf(dsq, 1e-12f);
    float r = __uint_as_float(0x5f37642fu - (__float_as_uint(dsq) >> 1));
    r = r * fmaf(-0.5f * dsq * r, r, 1.5f);
    r = r * fmaf(-0.5f * dsq * r, r, 1.5f);
    return -(dsq * r);
}

// bf16 tensor-core GEMM (VALIDATED R11-R13 mainloop): KS=64 -> 64 MMAs/barrier
__global__ __launch_bounds__(256)
void gemm_bf16(float* __restrict__ dist) {
    extern __shared__ __nv_bfloat16 smem[];
    __nv_bfloat16* As = smem;                            // [NSTAGE][BM][LDA]
    __nv_bfloat16* Bs = smem + NSTAGE * BM * LDA;        // [NSTAGE][BN][LDA]

    int tid = threadIdx.x;
    int wid = tid >> 5, lane = tid & 31;
    int warp_m = wid >> 2, warp_n = wid & 3;             // 2 x 4 warps, warp tile 64x32
    int bm = blockIdx.y * BM, bn = blockIdx.x * BN;

    int lr = tid >> 3;
    int ls = tid & 7;
    const __nv_bfloat16* xg = g_xb + (size_t)bm * DIM;
    const __nv_bfloat16* eg = g_eb + (size_t)bn * DIM;

    float acc[4][4][4] = {};

    auto issue = [&](int kt, int s) {
        const __nv_bfloat16* xsrc = xg + kt * KS;
        const __nv_bfloat16* esrc = eg + kt * KS;
        __nv_bfloat16* Ad = As + (size_t)s * BM * LDA;
        __nv_bfloat16* Bd = Bs + (size_t)s * BN * LDA;
        #pragma unroll
        for (int t = 0; t < 4; t++) {
            int row = lr + t * 32;
            cp16(Ad + row * LDA + ls * 8, xsrc + (size_t)row * DIM + ls * 8);
            cp16(Bd + row * LDA + ls * 8, esrc + (size_t)row * DIM + ls * 8);
        }
    };

    issue(0, 0); CP_COMMIT();
    issue(1, 1); CP_COMMIT();

    int sc = 0, si = 2;
    #pragma unroll 1
    for (int kt = 0; kt < KT; kt++) {
        CP_WAIT1();
        __syncthreads();
        if (kt + NSTAGE - 1 < KT) issue(kt + NSTAGE - 1, si);
        CP_COMMIT();

        const __nv_bfloat16* Ab = As + (size_t)sc * BM * LDA;
        const __nv_bfloat16* Bb = Bs + (size_t)sc * BN * LDA;
        #pragma unroll
        for (int kk = 0; kk < 4; kk++) {
            unsigned a[4][4], b[4][2];
            #pragma unroll
            for (int mi = 0; mi < 4; mi++)
                ldsm_x4(a[mi][0], a[mi][1], a[mi][2], a[mi][3],
                        Ab + (warp_m * 64 + mi * 16 + (lane & 15)) * LDA
                           + kk * 16 + ((lane >> 4) << 3));
            #pragma unroll
            for (int nib = 0; nib < 2; nib++) {
                unsigned r0, r1, r2, r3;
                ldsm_x4(r0, r1, r2, r3,
                        Bb + (warp_n * 32 + nib * 16 + ((lane >> 4) << 3) + (lane & 7)) * LDA
                           + kk * 16 + (((lane >> 3) & 1) << 3));
                b[nib * 2][0] = r0; b[nib * 2][1] = r1;
                b[nib * 2 + 1][0] = r2; b[nib * 2 + 1][1] = r3;
            }
            #pragma unroll
            for (int mi = 0; mi < 4; mi++)
                #pragma unroll
                for (int ni = 0; ni < 4; ni++)
                    mma_bf16(acc[mi][ni], a[mi], b[ni]);
        }
        sc = (sc + 1 == NSTAGE) ? 0 : sc + 1;
        si = (si + 1 == NSTAGE) ? 0 : si + 1;
    }

    // epilogue: dist (streaming stores) + per-(row, col-block) max via smem
    int qr = lane >> 2, qc = 2 * (lane & 3);
    float x2v[4][2], rmax[4][2];
    #pragma unroll
    for (int mi = 0; mi < 4; mi++)
        #pragma unroll
        for (int h = 0; h < 2; h++) {
            x2v[mi][h] = g_x2[bm + warp_m * 64 + mi * 16 + h * 8 + qr];
            rmax[mi][h] = -1e30f;
        }

    #pragma unroll
    for (int ni = 0; ni < 4; ni++) {
        int n0 = bn + warp_n * 32 + ni * 8 + qc;
        float y0 = g_y2[n0], y1 = g_y2[n0 + 1];
        #pragma unroll
        for (int mi = 0; mi < 4; mi++)
            #pragma unroll
            for (int h = 0; h < 2; h++) {
                int rg = bm + warp_m * 64 + mi * 16 + h * 8 + qr;
                float d0 = negdist(x2v[mi][h], y0, acc[mi][ni][2 * h]);
                float d1 = negdist(x2v[mi][h], y1, acc[mi][ni][2 * h + 1]);
                __stcs(reinterpret_cast<float2*>(&dist[(size_t)rg * NCODE + n0]),
                       make_float2(d0, d1));
                rmax[mi][h] = fmaxf(rmax[mi][h], fmaxf(d0, d1));
            }
    }

    // smem reduction across the 4 warp_n warps (no atomics, no init kernel)
    float* s_rm = reinterpret_cast<float*>(smem);    // [4][BM] = 2KB
    __syncthreads();
    #pragma unroll
    for (int mi = 0; mi < 4; mi++)
        #pragma unroll
        for (int h = 0; h < 2; h++) {
            float v = rmax[mi][h];
            v = fmaxf(v, __shfl_xor_sync(0xffffffffu, v, 1));
            v = fmaxf(v, __shfl_xor_sync(0xffffffffu, v, 2));
            if ((lane & 3) == 0)
                s_rm[warp_n * BM + warp_m * 64 + mi * 16 + h * 8 + qr] = v;
        }
    __syncthreads();
    if (tid < BM) {
        float v = fmaxf(fmaxf(s_rm[tid], s_rm[BM + tid]),
                        fmaxf(s_rm[2 * BM + tid], s_rm[3 * BM + tid]));
        g_colmax[(size_t)(bm + tid) * NCB + blockIdx.x] = fkey(v);
    }
}

// one warp per row: approx row max from the 64 block maxima, scan ONLY
// qualifying blocks, re-evaluate with the EXACT validated chain, write out_ind,
// gather embed row into out_q (finalize fused).
#define RWARPS 8
__global__ __launch_bounds__(256)
void rescue(const float* __restrict__ x, const float* __restrict__ e,
            const float* __restrict__ dist,
            float* __restrict__ out_q, float* __restrict__ out_ind) {
    __shared__ int s_cnt[RWARPS];
    __shared__ int s_cand[RWARPS][MAXCAND];

    int w = threadIdx.x >> 5, lane = threadIdx.x & 31;
    int row = blockIdx.x * RWARPS + w;

    if (lane == 0) s_cnt[w] = 0;
    __syncwarp();

    float cm0 = fkey_inv(g_colmax[(size_t)row * NCB + lane]);
    float cm1 = fkey_inv(g_colmax[(size_t)row * NCB + 32 + lane]);
    float m = fmaxf(cm0, cm1);
    #pragma unroll
    for (int off = 16; off > 0; off >>= 1)
        m = fmaxf(m, __shfl_xor_sync(0xffffffffu, m, off));
    float thr = m - MARGIN;

    const float* dp = dist + (size_t)row * NCODE;
    #pragma unroll 1
    for (int b = 0; b < NCB; b++) {
        float cb = (b < 32) ? __shfl_sync(0xffffffffu, cm0, b)
                            : __shfl_sync(0xffffffffu, cm1, b - 32);
        if (cb >= thr) {
            float4 v = *reinterpret_cast<const float4*>(dp + b * BN + lane * 4);
            #pragma unroll
            for (int q = 0; q < 4; q++) {
                float dv = (q == 0) ? v.x : (q == 1) ? v.y : (q == 2) ? v.z : v.w;
                if (dv >= thr) {
                    int slot = atomicAdd(&s_cnt[w], 1);
                    if (slot < MAXCAND) s_cand[w][slot] = b * BN + lane * 4 + q;
                }
            }
        }
    }
    __syncwarp();
    int cnt = s_cnt[w];
    if (cnt > MAXCAND) cnt = MAXCAND;

    unsigned long long key = 0ull;
    if (lane < cnt) {
        int c = s_cand[w][lane];
        const float* xr = x + (size_t)row * DIM;
        const float* er = e + (size_t)c * DIM;
        float s = 0.0f;
        #pragma unroll 8
        for (int k = 0; k < DIM; k++)          // strictly ascending-k fp32 FMA chain
            s = fmaf(xr[k], er[k], s);
        float xyv = __fmul_rn(-2.0f, s);
        float t   = __fadd_rn(g_x2[row], g_y2[c]);
        float dsq = __fadd_rn(t, xyv);
        float dv  = -sqrtf(fmaxf(dsq, 0.0f));
        key = ((unsigned long long)fkey(dv) << 32) | (unsigned int)(NCODE - 1 - c);
    }
    #pragma unroll
    for (int off = 16; off > 0; off >>= 1) {
        unsigned long long o = __shfl_xor_sync(0xffffffffu, key, off);
        key = (o > key) ? o : key;
    }
    int best = (NCODE - 1) - (int)(unsigned int)(__shfl_sync(0xffffffffu, key, 0) & 0xFFFFFFFFull);

    if (lane == 0) out_ind[row] = (float)best;
    const float4* src = reinterpret_cast<const float4*>(e + (size_t)best * DIM);
    float4* dst = reinterpret_cast<float4*>(out_q + (size_t)row * DIM);
    #pragma unroll
    for (int j = 0; j < DIM / 4 / 32; j++)
        __stcs(&dst[lane + 32 * j], src[lane + 32 * j]);
}

extern "C" void kernel_launch(void* const* d_in, const int* in_sizes, int n_in,
                              void* d_out, int out_size) {
    const float* x = (const float*)d_in[0];      // [32768, 512]
    const float* e = (const float*)d_in[1];      // [8192, 512]
    float* out = (float*)d_out;

    float* out_q    = out;                                   // [N, D]
    float* out_ind  = out + (size_t)NROWS * DIM;             // [N]
    float* out_dist = out + (size_t)NROWS * DIM + NROWS;     // [N, C]

    cudaFuncSetAttribute(gemm_bf16, cudaFuncAttributeMaxDynamicSharedMemorySize, SMEM_BYTES);

    conv_norm_all<<<(NROWS + NCODE) / 128, 128>>>(x, e);

    dim3 grid(NCODE / BN, NROWS / BM);
    gemm_bf16<<<grid, 256, SMEM_BYTES>>>(out_dist);

    rescue<<<NROWS / RWARPS, 256>>>(x, e, out_dist, out_q, out_ind);
}

// round 15
// speedup vs baseline: 2.0434x; 1.1190x over previous
#include <cuda_runtime.h>
#include <cuda_bf16.h>
#include <math.h>

#define NROWS 32768
#define NCODE 8192
#define DIM   512

#define BM 128
#define BN 128
#define NCB (NCODE / BN)   // 64 column blocks
#define KS 64
#define KT (DIM / KS)      // 8
#define NSTAGE 3
#define LDA 72          // KS + 8 pad (bf16): 144B row stride -> conflict-free ldmatrix

#define MARGIN 0.02f
#define MAXCAND 32

#define SMEM_BYTES (NSTAGE * (BM + BN) * LDA * 2)   // 110592

// scratch (no allocations allowed)
__device__ float g_x2[NROWS];
__device__ float g_y2[NCODE];
__device__ unsigned int g_colmax[NROWS * NCB];   // fkey of per-(row, col-block) max
__device__ __nv_bfloat16 g_xb[NROWS * DIM];
__device__ __nv_bfloat16 g_eb[NCODE * DIM];

__device__ __forceinline__ unsigned int fkey(float v) {
    unsigned int b = __float_as_uint(v);
    return (b & 0x80000000u) ? ~b : (b | 0x80000000u);
}
__device__ __forceinline__ float fkey_inv(unsigned int k) {
    unsigned int b = (k & 0x80000000u) ? (k & 0x7FFFFFFFu) : ~k;
    return __uint_as_float(b);
}

__device__ __forceinline__ void cp16(void* dst, const void* src) {
    unsigned d = (unsigned)__cvta_generic_to_shared(dst);
    asm volatile("cp.async.cg.shared.global [%0], [%1], 16;" :: "r"(d), "l"(src));
}
#define CP_COMMIT() asm volatile("cp.async.commit_group;")
#define CP_WAIT1()  asm volatile("cp.async.wait_group 1;")
#define CP_WAIT0()  asm volatile("cp.async.wait_group 0;")

// FUSED bf16 convert + strictly sequential scalar fp32 norm, smem-staged,
// double-buffered via cp.async. Chunks ascend in k and the per-row chain is
// the identical __fadd_rn(s, __fmul_rn(v,v)) ascending sequence as R5-R14
// -> the norm value is BITWISE IDENTICAL to the validated one.
// Block = 128 threads = 128 rows; 8 chunks of 64 columns.
#define CLD 68   // 68 floats = 272B row stride: 16B-aligned, 4-way worst conflict
__global__ __launch_bounds__(128)
void conv_norm_all(const float* __restrict__ x, const float* __restrict__ e) {
    __shared__ float sb[2][128][CLD];

    int t = threadIdx.x;
    int blk = blockIdx.x;              // 0..255 -> x rows, 256..319 -> e rows
    const float* src;
    __nv_bfloat16* dst;
    float* outp;
    int row0;
    if (blk < NROWS / 128) {
        row0 = blk * 128;
        src = x + (size_t)row0 * DIM;
        dst = g_xb + (size_t)row0 * DIM;
        outp = g_x2 + row0;
    } else {
        row0 = (blk - NROWS / 128) * 128;
        src = e + (size_t)row0 * DIM;
        dst = g_eb + (size_t)row0 * DIM;
        outp = g_y2 + row0;
    }

    // issue chunk c into buffer b: 128 rows x 64 floats, 16B granules
    auto issue = [&](int c, int b) {
        #pragma unroll
        for (int i = 0; i < 16; i++) {
            int id = t + i * 128;
            int r = id >> 4, sg = id & 15;
            cp16(&sb[b][r][sg * 4], src + (size_t)r * DIM + c * 64 + sg * 4);
        }
    };

    issue(0, 0); CP_COMMIT();

    float s = 0.0f;
    #pragma unroll 1
    for (int c = 0; c < 8; c++) {
        int cur = c & 1;
        if (c + 1 < 8) { issue(c + 1, (c + 1) & 1); CP_COMMIT(); CP_WAIT1(); }
        else { CP_WAIT0(); }
        __syncthreads();                       // chunk c visible

        // strictly sequential fp32 chain on own row (ascending k)
        #pragma unroll 8
        for (int k = 0; k < 64; k++) {
            float v = sb[cur][t][k];
            s = __fadd_rn(s, __fmul_rn(v, v));
        }

        // cooperative coalesced bf16 store: warp writes one row's 128B chunk
        #pragma unroll
        for (int i = 0; i < 32; i++) {
            int id = t + i * 128;
            int r = id >> 5, sg = id & 31;
            __nv_bfloat162 pr = __floats2bfloat162_rn(sb[cur][r][sg * 2],
                                                      sb[cur][r][sg * 2 + 1]);
            *reinterpret_cast<__nv_bfloat162*>(
                dst + (size_t)r * DIM + c * 64 + sg * 2) = pr;
        }
        __syncthreads();                       // done reading before buffer reuse
    }
    outp[t] = s;
}

__device__ __forceinline__ void ldsm_x4(unsigned& r0, unsigned& r1, unsigned& r2, unsigned& r3,
                                        const void* ptr) {
    unsigned addr = (unsigned)__cvta_generic_to_shared(ptr);
    asm volatile("ldmatrix.sync.aligned.m8n8.x4.shared.b16 {%0,%1,%2,%3}, [%4];"
                 : "=r"(r0), "=r"(r1), "=r"(r2), "=r"(r3) : "r"(addr));
}
__device__ __forceinline__ void mma_bf16(float* c, const unsigned* a, const unsigned* b) {
    asm volatile(
        "mma.sync.aligned.m16n8k16.row.col.f32.bf16.bf16.f32 "
        "{%0,%1,%2,%3}, {%4,%5,%6,%7}, {%8,%9}, {%0,%1,%2,%3};"
        : "+f"(c[0]), "+f"(c[1]), "+f"(c[2]), "+f"(c[3])
        : "r"(a[0]), "r"(a[1]), "r"(a[2]), "r"(a[3]), "r"(b[0]), "r"(b[1]));
}

// fast sqrt on the FMA pipe (no MUFU): rsqrt bit-hack + 2 Newton, ~4e-6 rel.
__device__ __forceinline__ float negdist(float x2, float y2, float sxy) {
    float dsq = __fadd_rn(__fadd_rn(x2, y2), __fmul_rn(-2.0f, sxy));
    dsq = fmaxf(dsq, 1e-12f);
    float r = __uint_as_float(0x5f37642fu - (__float_as_uint(dsq) >> 1));
    r = r * fmaf(-0.5f * dsq * r, r, 1.5f);
    r = r * fmaf(-0.5f * dsq * r, r, 1.5f);
    return -(dsq * r);
}

// bf16 tensor-core GEMM (VALIDATED R11-R14 mainloop): KS=64 -> 64 MMAs/barrier
__global__ __launch_bounds__(256)
void gemm_bf16(float* __restrict__ dist) {
    extern __shared__ __nv_bfloat16 smem[];
    __nv_bfloat16* As = smem;                            // [NSTAGE][BM][LDA]
    __nv_bfloat16* Bs = smem + NSTAGE * BM * LDA;        // [NSTAGE][BN][LDA]

    int tid = threadIdx.x;
    int wid = tid >> 5, lane = tid & 31;
    int warp_m = wid >> 2, warp_n = wid & 3;             // 2 x 4 warps, warp tile 64x32
    int bm = blockIdx.y * BM, bn = blockIdx.x * BN;

    int lr = tid >> 3;
    int ls = tid & 7;
    const __nv_bfloat16* xg = g_xb + (size_t)bm * DIM;
    const __nv_bfloat16* eg = g_eb + (size_t)bn * DIM;

    float acc[4][4][4] = {};

    auto issue = [&](int kt, int s) {
        const __nv_bfloat16* xsrc = xg + kt * KS;
        const __nv_bfloat16* esrc = eg + kt * KS;
        __nv_bfloat16* Ad = As + (size_t)s * BM * LDA;
        __nv_bfloat16* Bd = Bs + (size_t)s * BN * LDA;
        #pragma unroll
        for (int t = 0; t < 4; t++) {
            int row = lr + t * 32;
            cp16(Ad + row * LDA + ls * 8, xsrc + (size_t)row * DIM + ls * 8);
            cp16(Bd + row * LDA + ls * 8, esrc + (size_t)row * DIM + ls * 8);
        }
    };

    issue(0, 0); CP_COMMIT();
    issue(1, 1); CP_COMMIT();

    int sc = 0, si = 2;
    #pragma unroll 1
    for (int kt = 0; kt < KT; kt++) {
        CP_WAIT1();
        __syncthreads();
        if (kt + NSTAGE - 1 < KT) issue(kt + NSTAGE - 1, si);
        CP_COMMIT();

        const __nv_bfloat16* Ab = As + (size_t)sc * BM * LDA;
        const __nv_bfloat16* Bb = Bs + (size_t)sc * BN * LDA;
        #pragma unroll
        for (int kk = 0; kk < 4; kk++) {
            unsigned a[4][4], b[4][2];
            #pragma unroll
            for (int mi = 0; mi < 4; mi++)
                ldsm_x4(a[mi][0], a[mi][1], a[mi][2], a[mi][3],
                        Ab + (warp_m * 64 + mi * 16 + (lane & 15)) * LDA
                           + kk * 16 + ((lane >> 4) << 3));
            #pragma unroll
            for (int nib = 0; nib < 2; nib++) {
                unsigned r0, r1, r2, r3;
                ldsm_x4(r0, r1, r2, r3,
                        Bb + (warp_n * 32 + nib * 16 + ((lane >> 4) << 3) + (lane & 7)) * LDA
                           + kk * 16 + (((lane >> 3) & 1) << 3));
                b[nib * 2][0] = r0; b[nib * 2][1] = r1;
                b[nib * 2 + 1][0] = r2; b[nib * 2 + 1][1] = r3;
            }
            #pragma unroll
            for (int mi = 0; mi < 4; mi++)
                #pragma unroll
                for (int ni = 0; ni < 4; ni++)
                    mma_bf16(acc[mi][ni], a[mi], b[ni]);
        }
        sc = (sc + 1 == NSTAGE) ? 0 : sc + 1;
        si = (si + 1 == NSTAGE) ? 0 : si + 1;
    }

    // epilogue: dist (streaming stores) + per-(row, col-block) max via smem
    int qr = lane >> 2, qc = 2 * (lane & 3);
    float x2v[4][2], rmax[4][2];
    #pragma unroll
    for (int mi = 0; mi < 4; mi++)
        #pragma unroll
        for (int h = 0; h < 2; h++) {
            x2v[mi][h] = g_x2[bm + warp_m * 64 + mi * 16 + h * 8 + qr];
            rmax[mi][h] = -1e30f;
        }

    #pragma unroll
    for (int ni = 0; ni < 4; ni++) {
        int n0 = bn + warp_n * 32 + ni * 8 + qc;
        float y0 = g_y2[n0], y1 = g_y2[n0 + 1];
        #pragma unroll
        for (int mi = 0; mi < 4; mi++)
            #pragma unroll
            for (int h = 0; h < 2; h++) {
                int rg = bm + warp_m * 64 + mi * 16 + h * 8 + qr;
                float d0 = negdist(x2v[mi][h], y0, acc[mi][ni][2 * h]);
                float d1 = negdist(x2v[mi][h], y1, acc[mi][ni][2 * h + 1]);
                __stcs(reinterpret_cast<float2*>(&dist[(size_t)rg * NCODE + n0]),
                       make_float2(d0, d1));
                rmax[mi][h] = fmaxf(rmax[mi][h], fmaxf(d0, d1));
            }
    }

    // smem reduction across the 4 warp_n warps (no atomics, no init kernel)
    float* s_rm = reinterpret_cast<float*>(smem);    // [4][BM] = 2KB
    __syncthreads();
    #pragma unroll
    for (int mi = 0; mi < 4; mi++)
        #pragma unroll
        for (int h = 0; h < 2; h++) {
            float v = rmax[mi][h];
            v = fmaxf(v, __shfl_xor_sync(0xffffffffu, v, 1));
            v = fmaxf(v, __shfl_xor_sync(0xffffffffu, v, 2));
            if ((lane & 3) == 0)
                s_rm[warp_n * BM + warp_m * 64 + mi * 16 + h * 8 + qr] = v;
        }
    __syncthreads();
    if (tid < BM) {
        float v = fmaxf(fmaxf(s_rm[tid], s_rm[BM + tid]),
                        fmaxf(s_rm[2 * BM + tid], s_rm[3 * BM + tid]));
        g_colmax[(size_t)(bm + tid) * NCB + blockIdx.x] = fkey(v);
    }
}

// one warp per row: approx row max from the 64 block maxima, scan ONLY
// qualifying blocks, re-evaluate with the EXACT validated chain, write out_ind,
// gather embed row into out_q (finalize fused).
#define RWARPS 8
__global__ __launch_bounds__(256)
void rescue(const float* __restrict__ x, const float* __restrict__ e,
            const float* __restrict__ dist,
            float* __restrict__ out_q, float* __restrict__ out_ind) {
    __shared__ int s_cnt[RWARPS];
    __shared__ int s_cand[RWARPS][MAXCAND];

    int w = threadIdx.x >> 5, lane = threadIdx.x & 31;
    int row = blockIdx.x * RWARPS + w;

    if (lane == 0) s_cnt[w] = 0;
    __syncwarp();

    float cm0 = fkey_inv(g_colmax[(size_t)row * NCB + lane]);
    float cm1 = fkey_inv(g_colmax[(size_t)row * NCB + 32 + lane]);
    float m = fmaxf(cm0, cm1);
    #pragma unroll
    for (int off = 16; off > 0; off >>= 1)
        m = fmaxf(m, __shfl_xor_sync(0xffffffffu, m, off));
    float thr = m - MARGIN;

    const float* dp = dist + (size_t)row * NCODE;
    #pragma unroll 1
    for (int b = 0; b < NCB; b++) {
        float cb = (b < 32) ? __shfl_sync(0xffffffffu, cm0, b)
                            : __shfl_sync(0xffffffffu, cm1, b - 32);
        if (cb >= thr) {
            float4 v = *reinterpret_cast<const float4*>(dp + b * BN + lane * 4);
            #pragma unroll
            for (int q = 0; q < 4; q++) {
                float dv = (q == 0) ? v.x : (q == 1) ? v.y : (q == 2) ? v.z : v.w;
                if (dv >= thr) {
                    int slot = atomicAdd(&s_cnt[w], 1);
                    if (slot < MAXCAND) s_cand[w][slot] = b * BN + lane * 4 + q;
                }
            }
        }
    }
    __syncwarp();
    int cnt = s_cnt[w];
    if (cnt > MAXCAND) cnt = MAXCAND;

    unsigned long long key = 0ull;
    if (lane < cnt) {
        int c = s_cand[w][lane];
        const float* xr = x + (size_t)row * DIM;
        const float* er = e + (size_t)c * DIM;
        // EXACT validated chain: strictly ascending-k fp32 FMA sequence,
        // now fed by float4 loads (identical op order -> bitwise identical).
        float s = 0.0f;
        #pragma unroll 4
        for (int k = 0; k < DIM; k += 4) {
            float4 xa = *reinterpret_cast<const float4*>(xr + k);
            float4 ea = *reinterpret_cast<const float4*>(er + k);
            s = fmaf(xa.x, ea.x, s);
            s = fmaf(xa.y, ea.y, s);
            s = fmaf(xa.z, ea.z, s);
            s = fmaf(xa.w, ea.w, s);
        }
        float xyv = __fmul_rn(-2.0f, s);
        float t   = __fadd_rn(g_x2[row], g_y2[c]);
        float dsq = __fadd_rn(t, xyv);
        float dv  = -sqrtf(fmaxf(dsq, 0.0f));
        key = ((unsigned long long)fkey(dv) << 32) | (unsigned int)(NCODE - 1 - c);
    }
    #pragma unroll
    for (int off = 16; off > 0; off >>= 1) {
        unsigned long long o = __shfl_xor_sync(0xffffffffu, key, off);
        key = (o > key) ? o : key;
    }
    int best = (NCODE - 1) - (int)(unsigned int)(__shfl_sync(0xffffffffu, key, 0) & 0xFFFFFFFFull);

    if (lane == 0) out_ind[row] = (float)best;
    const float4* src = reinterpret_cast<const float4*>(e + (size_t)best * DIM);
    float4* dst = reinterpret_cast<float4*>(out_q + (size_t)row * DIM);
    #pragma unroll
    for (int j = 0; j < DIM / 4 / 32; j++)
        __stcs(&dst[lane + 32 * j], src[lane + 32 * j]);
}

extern "C" void kernel_launch(void* const* d_in, const int* in_sizes, int n_in,
                              void* d_out, int out_size) {
    const float* x = (const float*)d_in[0];      // [32768, 512]
    const float* e = (const float*)d_in[1];      // [8192, 512]
    float* out = (float*)d_out;

    float* out_q    = out;                                   // [N, D]
    float* out_ind  = out + (size_t)NROWS * DIM;             // [N]
    float* out_dist = out + (size_t)NROWS * DIM + NROWS;     // [N, C]

    cudaFuncSetAttribute(gemm_bf16, cudaFuncAttributeMaxDynamicSharedMemorySize, SMEM_BYTES);

    conv_norm_all<<<(NROWS + NCODE) / 128, 128>>>(x, e);

    dim3 grid(NCODE / BN, NROWS / BM);
    gemm_bf16<<<grid, 256, SMEM_BYTES>>>(out_dist);

    rescue<<<NROWS / RWARPS, 256>>>(x, e, out_dist, out_q, out_ind);
}